// round 11
// baseline (speedup 1.0000x reference)
#include <cuda_runtime.h>
#include <cuda_bf16.h>
#include <cuda_fp16.h>
#include <cstdint>

// ---------------- problem constants ----------------
#define BATCH 2
#define S_LEN 2048
#define PREV_LEN 1024
#define T_LEN 3072
#define DIM 2048
#define HEADS 16
#define HD 128
#define FF_DIM 8192
#define ROWS (BATCH * S_LEN)  // 4096
#define QK_SCALE 0.08838834764831845f

#define OUT_X_ELEMS  (BATCH * S_LEN * DIM)
#define OUT_KV_ELEMS (BATCH * HEADS * T_LEN * HD)

// ================= PTX helpers (portable sm_80+) ====
__device__ __forceinline__ uint32_t smem_u32(const void* p) {
    uint32_t a;
    asm("{ .reg .u64 t; cvta.to.shared.u64 t, %1; cvt.u32.u64 %0, t; }" : "=r"(a) : "l"(p));
    return a;
}
__device__ __forceinline__ void cp_async16(uint32_t smem, const void* g) {
    asm volatile("cp.async.cg.shared.global [%0], [%1], 16;" :: "r"(smem), "l"(g) : "memory");
}
#define CP_COMMIT() asm volatile("cp.async.commit_group;" ::: "memory")
#define CP_WAIT2()  asm volatile("cp.async.wait_group 2;" ::: "memory")
#define CP_WAIT1()  asm volatile("cp.async.wait_group 1;" ::: "memory")

__device__ __forceinline__ void ldsm4(uint32_t* r, uint32_t addr) {
    asm volatile("ldmatrix.sync.aligned.m8n8.x4.shared.b16 {%0,%1,%2,%3}, [%4];"
        : "=r"(r[0]), "=r"(r[1]), "=r"(r[2]), "=r"(r[3]) : "r"(addr));
}
__device__ __forceinline__ void ldsm4t(uint32_t* r, uint32_t addr) {
    asm volatile("ldmatrix.sync.aligned.m8n8.x4.trans.shared.b16 {%0,%1,%2,%3}, [%4];"
        : "=r"(r[0]), "=r"(r[1]), "=r"(r[2]), "=r"(r[3]) : "r"(addr));
}
__device__ __forceinline__ void mma_f16(float* c, const uint32_t* a, uint32_t b0, uint32_t b1) {
    asm volatile(
        "mma.sync.aligned.m16n8k16.row.col.f32.f16.f16.f32 "
        "{%0,%1,%2,%3}, {%4,%5,%6,%7}, {%8,%9}, {%0,%1,%2,%3};"
        : "+f"(c[0]), "+f"(c[1]), "+f"(c[2]), "+f"(c[3])
        : "r"(a[0]), "r"(a[1]), "r"(a[2]), "r"(a[3]), "r"(b0), "r"(b1));
}
__device__ __forceinline__ uint32_t pack_f16(float a, float b) {
    __half2 t = __floats2half2_rn(a, b);
    return *(uint32_t*)&t;
}

// ---------------- scratch (device globals) --------
__device__ float g_x1 [ROWS * DIM];
__device__ __half g_hA16 [ROWS * DIM];
__device__ __half g_h216 [ROWS * DIM];
__device__ __half g_o16  [ROWS * DIM];
__device__ __half g_gt16 [ROWS * FF_DIM];
__device__ __half g_q16 [ROWS * DIM];
__device__ __half g_k16 [OUT_KV_ELEMS];
__device__ __half g_v16 [OUT_KV_ELEMS];
__device__ __half g_wqkv[3 * DIM * DIM];
__device__ __half g_wo  [DIM * DIM];
__device__ __half g_wg  [DIM * FF_DIM];
__device__ __half g_wv2 [DIM * FF_DIM];
__device__ __half g_wp  [FF_DIM * DIM];

// =====================================================================
// Weight converter + transpose: W[K][N] fp32 -> Wt[N][K] fp16.
// =====================================================================
__device__ __forceinline__ void wconv_body(
    const float* __restrict__ W, __half* __restrict__ T16, int N, int K)
{
    __shared__ float tile[32][133];
    const int k0 = blockIdx.x * 32, n0 = blockIdx.y * 128;
    const int tid = threadIdx.x;
    {
        const int kr = tid >> 3;
        const int nq = (tid & 7) * 16;
        const float* src = W + (size_t)(k0 + kr) * N + n0 + nq;
        #pragma unroll
        for (int u = 0; u < 4; u++) {
            float4 v = *(const float4*)(src + u * 4);
            tile[kr][nq + u * 4 + 0] = v.x;
            tile[kr][nq + u * 4 + 1] = v.y;
            tile[kr][nq + u * 4 + 2] = v.z;
            tile[kr][nq + u * 4 + 3] = v.w;
        }
    }
    __syncthreads();
    const int n = tid >> 1;
    const int q = tid & 1;
    __align__(16) __half hv[16];
    #pragma unroll
    for (int u = 0; u < 16; u++)
        hv[u] = __float2half(tile[q * 16 + u][n]);
    const size_t off = (size_t)(n0 + n) * K + k0 + q * 16;
    *(uint4*)(T16 + off)     = *(const uint4*)(hv);
    *(uint4*)(T16 + off + 8) = *(const uint4*)(hv + 8);
}

__global__ __launch_bounds__(256) void weight_conv1(
    const float* __restrict__ W, __half* __restrict__ T, int N, int K)
{
    wconv_body(W, T, N, K);
}
__global__ __launch_bounds__(256) void weight_conv2(
    const float* __restrict__ W0, const float* __restrict__ W1,
    __half* __restrict__ T0, __half* __restrict__ T1, int N, int K)
{
    const float* W = blockIdx.z ? W1 : W0;
    __half* T = blockIdx.z ? T1 : T0;
    wconv_body(W, T, N, K);
}
__global__ __launch_bounds__(256) void weight_conv4(
    const float* __restrict__ W0, const float* __restrict__ W1,
    const float* __restrict__ W2, const float* __restrict__ W3,
    __half* __restrict__ T0, __half* __restrict__ T1,
    __half* __restrict__ T2, __half* __restrict__ T3, int N, int K)
{
    const int z = blockIdx.z;
    const float* W = (z == 0) ? W0 : (z == 1) ? W1 : (z == 2) ? W2 : W3;
    __half* T = (z == 0) ? T0 : (z == 1) ? T1 : (z == 2) ? T2 : T3;
    wconv_body(W, T, N, K);
}

// =====================================================================
// rmsnorm -> single fp16 row-major
// =====================================================================
__global__ __launch_bounds__(256) void rmsnorm_h(
    const float* __restrict__ x, const float* __restrict__ w,
    __half* __restrict__ O16)
{
    __shared__ float red[256];
    const int tid = threadIdx.x;
    const int m = blockIdx.x;
    const float* xp = x + (size_t)m * DIM + tid * 8;
    float4 a = *(const float4*)xp;
    float4 b = *(const float4*)(xp + 4);
    float s = a.x*a.x + a.y*a.y + a.z*a.z + a.w*a.w
            + b.x*b.x + b.y*b.y + b.z*b.z + b.w*b.w;
    red[tid] = s;
    __syncthreads();
    #pragma unroll
    for (int off = 128; off > 0; off >>= 1) {
        if (tid < off) red[tid] += red[tid + off];
        __syncthreads();
    }
    float scale = rsqrtf(red[0] * (1.0f / DIM) + 1e-6f);
    const float* wp = w + tid * 8;
    float4 wa = *(const float4*)wp;
    float4 wb = *(const float4*)(wp + 4);
    float y[8];
    y[0] = a.x*scale*wa.x; y[1] = a.y*scale*wa.y; y[2] = a.z*scale*wa.z; y[3] = a.w*scale*wa.w;
    y[4] = b.x*scale*wb.x; y[5] = b.y*scale*wb.y; y[6] = b.z*scale*wb.z; y[7] = b.w*scale*wb.w;
    __align__(16) __half hv[8];
    #pragma unroll
    for (int j = 0; j < 8; j++) hv[j] = __float2half(y[j]);
    *(uint4*)(O16 + (size_t)m * DIM + tid * 8) = *(const uint4*)hv;
}

// =====================================================================
// fp16 single-pass GEMM core. CTA 128x256, warp 64x64, 8 warps,
// K-chunk 64, 4-stage cp.async, single barrier per chunk.
// stage: A 16KB (128 rows x 128B) + B 32KB (256 rows x 128B) = 48KB.
// =====================================================================
#define GM_STAGES 4
#define GM_STAGE_BYTES 49152
#define GM_SMEM (GM_STAGES * GM_STAGE_BYTES)   // 196608
#define OFF_A 0
#define OFF_B 16384

// 128B-row swizzle: g = 16B column index (0..7), full 8-way XOR
__device__ __forceinline__ uint32_t swz128(int r, int g) {
    return (uint32_t)((r << 7) + (((g ^ (r & 7)) & 7) << 4));
}

template<typename IssueF>
__device__ __forceinline__ void gemm_mainloop(
    float (&acc)[4][8][4], uint32_t sb, int nk, int wm, int wn, int lane,
    IssueF issue_stage)
{
    issue_stage(0, 0); CP_COMMIT();
    issue_stage(1, 1); CP_COMMIT();
    issue_stage(2, 2); CP_COMMIT();

    for (int kc = 0; kc < nk; kc++) {
        CP_WAIT2();
        __syncthreads();
        if (kc + 3 < nk) issue_stage(kc + 3, (kc + 3) & 3);
        CP_COMMIT();

        const uint32_t st = sb + (kc & 3) * GM_STAGE_BYTES;
        #pragma unroll
        for (int h = 0; h < 4; h++) {
            uint32_t a[4][4];
            #pragma unroll
            for (int mi = 0; mi < 4; mi++) {
                const int r = wm * 64 + mi * 16 + (lane & 15);
                ldsm4(a[mi], st + OFF_A + swz128(r, h * 2 + (lane >> 4)));
            }
            #pragma unroll
            for (int ng = 0; ng < 4; ng++) {
                uint32_t b[4];
                const int r = wn * 64 + ng * 16 + (lane & 15);
                ldsm4(b, st + OFF_B + swz128(r, h * 2 + (lane >> 4)));
                #pragma unroll
                for (int mi = 0; mi < 4; mi++) {
                    mma_f16(acc[mi][ng * 2 + 0], a[mi], b[0], b[2]);
                    mma_f16(acc[mi][ng * 2 + 1], a[mi], b[1], b[3]);
                }
            }
        }
        // no trailing sync: next iteration's issue targets the slot whose
        // reads completed before this iteration's top barrier.
    }
}

// per-stage loads: A rows 0..127 (4 chunks/thread), B rows 0..255 (8/thread)
#define GEMM_ISSUE_LAMBDA(A16, B16, m0, n0, K)                                  \
    auto issue_stage = [&](int kc, int slot) {                                  \
        const uint32_t st = sb + slot * GM_STAGE_BYTES;                         \
        const int r0 = tid >> 1;                                                \
        const int g0 = (tid & 1) * 4;                                           \
        const int kbase = kc * 64;                                              \
        _Pragma("unroll")                                                       \
        for (int u = 0; u < 4; u++) {                                           \
            const int g = g0 + u;                                               \
            cp_async16(st + OFF_A + swz128(r0, g),                              \
                       A16 + (size_t)(m0 + r0) * K + kbase + g * 8);            \
        }                                                                       \
        _Pragma("unroll")                                                       \
        for (int i = 0; i < 2; i++) {                                           \
            const int r = r0 + i * 128;                                         \
            _Pragma("unroll")                                                   \
            for (int u = 0; u < 4; u++) {                                       \
                const int g = g0 + u;                                           \
                cp_async16(st + OFF_B + swz128(r, g),                           \
                           B16 + (size_t)(n0 + r) * K + kbase + g * 8);         \
            }                                                                   \
        }                                                                       \
    };

// =====================================================================
// Generic GEMM (MODE 1): C = A@B + bias + extra (fp32 out)
// =====================================================================
template<int MODE>
__global__ void __launch_bounds__(256, 1) gemm_mma(
    const __half* __restrict__ A16, const __half* __restrict__ B16,
    const float* __restrict__ bias, const float* __restrict__ extra,
    float* __restrict__ C, __half* __restrict__ C16,
    int M, int N, int K)
{
    extern __shared__ char smraw[];
    const uint32_t sb = smem_u32(smraw);
    const int tid = threadIdx.x;
    const int wid = tid >> 5;
    const int lane = tid & 31;
    const int wm = wid & 1;
    const int wn = wid >> 1;
    const int m0 = blockIdx.y * 128;
    const int n0 = blockIdx.x * 256;
    const int nk = K >> 6;

    float acc[4][8][4];
    #pragma unroll
    for (int a = 0; a < 4; a++)
        #pragma unroll
        for (int b = 0; b < 8; b++)
            #pragma unroll
            for (int c = 0; c < 4; c++) acc[a][b][c] = 0.f;

    GEMM_ISSUE_LAMBDA(A16, B16, m0, n0, K)
    gemm_mainloop(acc, sb, nk, wm, wn, lane, issue_stage);

    const int mb = m0 + wm * 64;
    const int nb = n0 + wn * 64;
    #pragma unroll
    for (int mi = 0; mi < 4; mi++) {
        #pragma unroll
        for (int j = 0; j < 8; j++) {
            const int row = mb + mi * 16 + (lane >> 2);
            const int col = nb + j * 8 + (lane & 3) * 2;
            const float b0 = bias[col], b1 = bias[col + 1];
            #pragma unroll
            for (int half = 0; half < 2; half++) {
                const int rr = row + half * 8;
                float v0 = acc[mi][j][half * 2 + 0] + b0;
                float v1 = acc[mi][j][half * 2 + 1] + b1;
                if (MODE == 1) {
                    const float* ep = extra + (size_t)rr * N + col;
                    v0 += ep[0]; v1 += ep[1];
                }
                *(float2*)(C + (size_t)rr * N + col) = make_float2(v0, v1);
            }
        }
    }
}

// =====================================================================
// Fused QKV GEMM: B = concat[wq|wk|wv] (N=6144). Epilogue: RoPE+relayout.
// =====================================================================
__global__ void __launch_bounds__(256, 1) gemm_qkv(
    const __half* __restrict__ A16, const __half* __restrict__ B16,
    const float* __restrict__ bq, const float* __restrict__ bk, const float* __restrict__ bv,
    const float* __restrict__ cosb, const float* __restrict__ sinb,
    float* __restrict__ out_k, float* __restrict__ out_v,
    __half* __restrict__ Q16, __half* __restrict__ K16, __half* __restrict__ V16)
{
    extern __shared__ char smraw[];
    const uint32_t sb = smem_u32(smraw);
    const int tid = threadIdx.x;
    const int wid = tid >> 5;
    const int lane = tid & 31;
    const int wm = wid & 1;
    const int wn = wid >> 1;
    const int m0 = blockIdx.y * 128;
    const int n0 = blockIdx.x * 256;
    const int K = DIM;
    const int nk = K >> 6;
    const int sec = n0 >> 11;
    const float* bias = (sec == 0) ? bq : ((sec == 1) ? bk : bv);

    float acc[4][8][4];
    #pragma unroll
    for (int a = 0; a < 4; a++)
        #pragma unroll
        for (int b = 0; b < 8; b++)
            #pragma unroll
            for (int c = 0; c < 4; c++) acc[a][b][c] = 0.f;

    GEMM_ISSUE_LAMBDA(A16, B16, m0, n0, K)
    gemm_mainloop(acc, sb, nk, wm, wn, lane, issue_stage);

    const int mb = m0 + wm * 64;
    const int nb = n0 + wn * 64;
    #pragma unroll
    for (int mi = 0; mi < 4; mi++) {
        #pragma unroll
        for (int j = 0; j < 8; j++) {
            const int row = mb + mi * 16 + (lane >> 2);
            const int col = nb + j * 8 + (lane & 3) * 2;
            const float b0 = bias[col & 2047], b1 = bias[(col & 2047) + 1];
            const int nc = col & 2047;
            const int h = nc >> 7;
            const int d = nc & 127;
            #pragma unroll
            for (int half = 0; half < 2; half++) {
                const int rr = row + half * 8;
                float v0 = acc[mi][j][half * 2 + 0] + b0;
                float v1 = acc[mi][j][half * 2 + 1] + b1;
                const int bi = rr >> 11;
                const int s = rr & 2047;
                if (sec < 2) {
                    const int i2 = d >> 1;
                    const float c = cosb[(PREV_LEN + s) * 64 + i2];
                    const float sn = sinb[(PREV_LEN + s) * 64 + i2];
                    const float r0 = v0 * c - v1 * sn;
                    const float r1 = v0 * sn + v1 * c;
                    if (sec == 0) {
                        *(__half2*)(Q16 + ((size_t)(bi * HEADS + h) * S_LEN + s) * HD + d) =
                            __floats2half2_rn(r0 * QK_SCALE, r1 * QK_SCALE);
                    } else {
                        const size_t off = ((size_t)(bi * HEADS + h) * T_LEN + PREV_LEN + s) * HD + d;
                        *(float2*)(out_k + off) = make_float2(r0, r1);
                        *(__half2*)(K16 + off) = __floats2half2_rn(r0, r1);
                    }
                } else {
                    const size_t off = ((size_t)(bi * HEADS + h) * T_LEN + PREV_LEN + s) * HD + d;
                    *(float2*)(out_v + off) = make_float2(v0, v1);
                    *(__half2*)(V16 + off) = __floats2half2_rn(v0, v1);
                }
            }
        }
    }
}

// =====================================================================
// Fused FFN gate+val GEMM: CTA 128(M)x128(N), K-chunk 64.
// stage: A 16K | Bg 16K | Bv 16K = 48KB, 4 stages.
// =====================================================================
#define FO_A  0
#define FO_BG 16384
#define FO_BV 32768

__global__ void __launch_bounds__(256, 1) gemm_ffn(
    const __half* __restrict__ A16,
    const __half* __restrict__ Bg, const __half* __restrict__ Bv,
    const float* __restrict__ bias_g, const float* __restrict__ bias_v,
    __half* __restrict__ C16)
{
    extern __shared__ char smraw[];
    const uint32_t sb = smem_u32(smraw);
    const int tid = threadIdx.x;
    const int wid = tid >> 5;
    const int lane = tid & 31;
    const int wm = wid & 1;
    const int wn = wid >> 1;
    const int m0 = blockIdx.y * 128;
    const int n0 = blockIdx.x * 128;
    const int K = DIM;
    const int nk = K >> 6;   // 32

    float ag[4][4][4], av[4][4][4];
    #pragma unroll
    for (int a = 0; a < 4; a++)
        #pragma unroll
        for (int b = 0; b < 4; b++)
            #pragma unroll
            for (int c = 0; c < 4; c++) { ag[a][b][c] = 0.f; av[a][b][c] = 0.f; }

    auto issue_stage = [&](int kc, int slot) {
        const uint32_t st = sb + slot * GM_STAGE_BYTES;
        const int r0 = tid >> 1;
        const int g0 = (tid & 1) * 4;
        const int kbase = kc * 64;
        #pragma unroll
        for (int u = 0; u < 4; u++) {
            const int g = g0 + u;
            const uint32_t sw = swz128(r0, g);
            const size_t go = (size_t)r0 * K + kbase + g * 8;
            cp_async16(st + FO_A  + sw, A16 + (size_t)m0 * K + go);
            cp_async16(st + FO_BG + sw, Bg  + (size_t)n0 * K + go);
            cp_async16(st + FO_BV + sw, Bv  + (size_t)n0 * K + go);
        }
    };

    issue_stage(0, 0); CP_COMMIT();
    issue_stage(1, 1); CP_COMMIT();
    issue_stage(2, 2); CP_COMMIT();

    for (int kc = 0; kc < nk; kc++) {
        CP_WAIT2();
        __syncthreads();
        if (kc + 3 < nk) issue_stage(kc + 3, (kc + 3) & 3);
        CP_COMMIT();

        const uint32_t st = sb + (kc & 3) * GM_STAGE_BYTES;
        #pragma unroll
        for (int h = 0; h < 4; h++) {
            uint32_t a[4][4];
            #pragma unroll
            for (int mi = 0; mi < 4; mi++) {
                const int r = wm * 64 + mi * 16 + (lane & 15);
                ldsm4(a[mi], st + FO_A + swz128(r, h * 2 + (lane >> 4)));
            }
            #pragma unroll
            for (int ng = 0; ng < 2; ng++) {
                const int r = wn * 32 + ng * 16 + (lane & 15);
                const uint32_t sw = swz128(r, h * 2 + (lane >> 4));
                uint32_t bg[4], bv[4];
                ldsm4(bg, st + FO_BG + sw);
                ldsm4(bv, st + FO_BV + sw);
                #pragma unroll
                for (int mi = 0; mi < 4; mi++) {
                    mma_f16(ag[mi][ng * 2 + 0], a[mi], bg[0], bg[2]);
                    mma_f16(ag[mi][ng * 2 + 1], a[mi], bg[1], bg[3]);
                    mma_f16(av[mi][ng * 2 + 0], a[mi], bv[0], bv[2]);
                    mma_f16(av[mi][ng * 2 + 1], a[mi], bv[1], bv[3]);
                }
            }
        }
    }

    const int mb = m0 + wm * 64;
    const int nb = n0 + wn * 32;
    #pragma unroll
    for (int mi = 0; mi < 4; mi++) {
        #pragma unroll
        for (int j = 0; j < 4; j++) {
            const int row = mb + mi * 16 + (lane >> 2);
            const int col = nb + j * 8 + (lane & 3) * 2;
            const float bg0 = bias_g[col], bg1 = bias_g[col + 1];
            const float bv0 = bias_v[col], bv1 = bias_v[col + 1];
            #pragma unroll
            for (int half = 0; half < 2; half++) {
                const int rr = row + half * 8;
                float gv0 = ag[mi][j][half * 2 + 0] + bg0;
                float gv1 = ag[mi][j][half * 2 + 1] + bg1;
                float vv0 = av[mi][j][half * 2 + 0] + bv0;
                float vv1 = av[mi][j][half * 2 + 1] + bv1;
                float o0 = gv0 / (1.f + __expf(-gv0)) * vv0;
                float o1 = gv1 / (1.f + __expf(-gv1)) * vv1;
                *(__half2*)(C16 + (size_t)rr * FF_DIM + col) = __floats2half2_rn(o0, o1);
            }
        }
    }
}

// ---------------- merged cache copy (z=0: K, z=1: V) ----------------
__global__ __launch_bounds__(256) void copy_cache2(
    const float* __restrict__ ink, const float* __restrict__ inv,
    float* __restrict__ outk, float* __restrict__ outv,
    __half* __restrict__ K16, __half* __restrict__ V16)
{
    const float* in = blockIdx.z ? inv : ink;
    float* out = blockIdx.z ? outv : outk;
    __half* H16 = blockIdx.z ? V16 : K16;
    int idx = blockIdx.x * 256 + threadIdx.x;   // 2^20 f4
    int bh  = idx >> 15;
    int rem = idx & 32767;
    float4 v = ((const float4*)in)[idx];
    size_t off4 = (size_t)bh * (T_LEN * HD / 4) + rem;
    ((float4*)out)[off4] = v;
    __align__(8) __half hv[4];
    hv[0] = __float2half(v.x); hv[1] = __float2half(v.y);
    hv[2] = __float2half(v.z); hv[3] = __float2half(v.w);
    *(uint2*)(H16 + off4 * 4) = *(const uint2*)hv;
}

// =====================================================================
// HMMA flash attention (unchanged, proven): fp16 1-pass QK, 3-stage KV.
// =====================================================================
#define FBM 128
#define FBN 64
#define F_OFF_Q  0
#define F_OFF_ST 32768
#define F_STAGE  32768
#define F_SMEM   (F_OFF_ST + 3 * F_STAGE)   // 131072

__device__ __forceinline__ uint32_t swz256(int r, int g) {
    return (uint32_t)((r << 8) + (((g ^ (r & 7)) & 15) << 4));
}

__global__ void __launch_bounds__(256) flash_mma(
    const __half* __restrict__ Q16, const __half* __restrict__ K16,
    const __half* __restrict__ V16, __half* __restrict__ O16)
{
    extern __shared__ char smraw[];
    const uint32_t sb = smem_u32(smraw);
    const int tid = threadIdx.x;
    const int wid = tid >> 5;
    const int lane = tid & 31;
    const int mtile = gridDim.x - 1 - blockIdx.x;
    const int bh = blockIdx.y;
    const int m0 = mtile * FBM;
    const int jend = (PREV_LEN + m0 + FBM) / FBN;
    const int mask_start = (PREV_LEN + m0) / FBN;

    {
        const size_t qo = ((size_t)bh * S_LEN + m0) * HD;
        for (int i = tid; i < 2048; i += 256) {
            int r = i >> 4, g = i & 15;
            cp_async16(sb + F_OFF_Q + swz256(r, g), Q16 + qo + (size_t)r * HD + g * 8);
        }
        CP_COMMIT();
    }

    auto issue_kv = [&](int jt, int slot) {
        const uint32_t st = sb + F_OFF_ST + slot * F_STAGE;
        const size_t ko = ((size_t)bh * T_LEN + jt * FBN) * HD;
        for (int i = tid; i < 1024; i += 256) {
            int r = i >> 4, g = i & 15;
            uint32_t sw = swz256(r, g);
            size_t go = ko + (size_t)r * HD + g * 8;
            cp_async16(st + sw, K16 + go);
            cp_async16(st + 16384 + sw, V16 + go);
        }
    };
    issue_kv(0, 0); CP_COMMIT();
    issue_kv(1, 1); CP_COMMIT();

    float of[16][4];
    #pragma unroll
    for (int i = 0; i < 16; i++)
        #pragma unroll
        for (int j = 0; j < 4; j++) of[i][j] = 0.f;
    float mrow0 = -1e30f, mrow1 = -1e30f, lrow0 = 0.f, lrow1 = 0.f;

    const int arow = wid * 16 + (lane & 15);
    const int agr  = lane >> 4;

    int slot = 0;
    int slot2 = 2;
    for (int jt = 0; jt < jend; jt++) {
        CP_WAIT1();
        __syncthreads();
        if (jt + 2 < jend) issue_kv(jt + 2, slot2);
        CP_COMMIT();

        const uint32_t st = sb + F_OFF_ST + slot * F_STAGE;
        const int t0 = jt * FBN;

        float sf[8][4];
        #pragma unroll
        for (int i = 0; i < 8; i++)
            #pragma unroll
            for (int j = 0; j < 4; j++) sf[i][j] = 0.f;

        #pragma unroll
        for (int kt = 0; kt < 8; kt++) {
            uint32_t a[4];
            ldsm4(a, sb + F_OFF_Q + swz256(arow, kt * 2 + agr));
            #pragma unroll
            for (int nb = 0; nb < 4; nb++) {
                uint32_t b[4];
                ldsm4(b, st + swz256(nb * 16 + (lane & 15), kt * 2 + agr));
                mma_f16(sf[nb * 2 + 0], a, b[0], b[2]);
                mma_f16(sf[nb * 2 + 1], a, b[1], b[3]);
            }
        }

        if (jt >= mask_start) {
            const int rb = m0 + wid * 16 + (lane >> 2);
            const int cb = t0 + (lane & 3) * 2;
            #pragma unroll
            for (int nt = 0; nt < 8; nt++) {
                const int c0 = cb + nt * 8;
                if (c0     > PREV_LEN + rb)     sf[nt][0] = -1e30f;
                if (c0 + 1 > PREV_LEN + rb)     sf[nt][1] = -1e30f;
                if (c0     > PREV_LEN + rb + 8) sf[nt][2] = -1e30f;
                if (c0 + 1 > PREV_LEN + rb + 8) sf[nt][3] = -1e30f;
            }
        }

        float mx0 = -1e30f, mx1 = -1e30f;
        #pragma unroll
        for (int nt = 0; nt < 8; nt++) {
            mx0 = fmaxf(mx0, fmaxf(sf[nt][0], sf[nt][1]));
            mx1 = fmaxf(mx1, fmaxf(sf[nt][2], sf[nt][3]));
        }
        mx0 = fmaxf(mx0, __shfl_xor_sync(0xFFFFFFFF, mx0, 1));
        mx0 = fmaxf(mx0, __shfl_xor_sync(0xFFFFFFFF, mx0, 2));
        mx1 = fmaxf(mx1, __shfl_xor_sync(0xFFFFFFFF, mx1, 1));
        mx1 = fmaxf(mx1, __shfl_xor_sync(0xFFFFFFFF, mx1, 2));
        const float nm0 = fmaxf(mrow0, mx0);
        const float nm1 = fmaxf(mrow1, mx1);
        const float al0 = __expf(mrow0 - nm0);
        const float al1 = __expf(mrow1 - nm1);
        mrow0 = nm0; mrow1 = nm1;

        float rs0 = 0.f, rs1 = 0.f;
        #pragma unroll
        for (int nt = 0; nt < 8; nt++) {
            sf[nt][0] = __expf(sf[nt][0] - nm0);
            sf[nt][1] = __expf(sf[nt][1] - nm0);
            sf[nt][2] = __expf(sf[nt][2] - nm1);
            sf[nt][3] = __expf(sf[nt][3] - nm1);
            rs0 += sf[nt][0] + sf[nt][1];
            rs1 += sf[nt][2] + sf[nt][3];
        }
        rs0 += __shfl_xor_sync(0xFFFFFFFF, rs0, 1);
        rs0 += __shfl_xor_sync(0xFFFFFFFF, rs0, 2);
        rs1 += __shfl_xor_sync(0xFFFFFFFF, rs1, 1);
        rs1 += __shfl_xor_sync(0xFFFFFFFF, rs1, 2);
        lrow0 = lrow0 * al0 + rs0;
        lrow1 = lrow1 * al1 + rs1;

        #pragma unroll
        for (int nt = 0; nt < 16; nt++) {
            of[nt][0] *= al0; of[nt][1] *= al0;
            of[nt][2] *= al1; of[nt][3] *= al1;
        }

        #pragma unroll
        for (int kt = 0; kt < 4; kt++) {
            uint32_t a[4];
            a[0] = pack_f16(sf[2 * kt][0],     sf[2 * kt][1]);
            a[1] = pack_f16(sf[2 * kt][2],     sf[2 * kt][3]);
            a[2] = pack_f16(sf[2 * kt + 1][0], sf[2 * kt + 1][1]);
            a[3] = pack_f16(sf[2 * kt + 1][2], sf[2 * kt + 1][3]);
            const int vrow = kt * 16 + ((lane >> 3) & 1) * 8 + (lane & 7);
            #pragma unroll
            for (int nb = 0; nb < 8; nb++) {
                uint32_t b[4];
                ldsm4t(b, st + 16384 + swz256(vrow, nb * 2 + ((lane >> 4) & 1)));
                mma_f16(of[nb * 2 + 0], a, b[0], b[1]);
                mma_f16(of[nb * 2 + 1], a, b[2], b[3]);
            }
        }
        slot  = (slot  == 2) ? 0 : slot + 1;
        slot2 = (slot2 == 2) ? 0 : slot2 + 1;
    }

    const float inv0 = 1.f / lrow0;
    const float inv1 = 1.f / lrow1;
    const int b = bh >> 4, h = bh & 15;
    const int r0 = m0 + wid * 16 + (lane >> 2);
    #pragma unroll
    for (int nt = 0; nt < 16; nt++) {
        const int gc = h * HD + nt * 8 + (lane & 3) * 2;
        *(__half2*)(O16 + (size_t)(b * S_LEN + r0) * DIM + gc) =
            __floats2half2_rn(of[nt][0] * inv0, of[nt][1] * inv0);
        *(__half2*)(O16 + (size_t)(b * S_LEN + r0 + 8) * DIM + gc) =
            __floats2half2_rn(of[nt][2] * inv1, of[nt][3] * inv1);
    }
}

// ---------------- launch ----------------
extern "C" void kernel_launch(void* const* d_in, const int* in_sizes, int n_in,
                              void* d_out, int out_size)
{
    const float* x          = (const float*)d_in[0];
    const float* k_cache    = (const float*)d_in[1];
    const float* v_cache    = (const float*)d_in[2];
    const float* attn_norm_w= (const float*)d_in[3];
    const float* ffn_norm_w = (const float*)d_in[4];
    const float* wq = (const float*)d_in[5];
    const float* bq = (const float*)d_in[6];
    const float* wk = (const float*)d_in[7];
    const float* bk = (const float*)d_in[8];
    const float* wv = (const float*)d_in[9];
    const float* bv = (const float*)d_in[10];
    const float* wo = (const float*)d_in[11];
    const float* bo = (const float*)d_in[12];
    const float* w_gate = (const float*)d_in[13];
    const float* b_gate = (const float*)d_in[14];
    const float* w_val  = (const float*)d_in[15];
    const float* b_val  = (const float*)d_in[16];
    const float* w_proj = (const float*)d_in[17];
    const float* b_proj = (const float*)d_in[18];
    const float* fcos   = (const float*)d_in[19];
    const float* fsin   = (const float*)d_in[20];

    float* out_x = (float*)d_out;
    float* out_k = out_x + OUT_X_ELEMS;
    float* out_v = out_k + OUT_KV_ELEMS;

    float *p_x1;
    __half *p_hA16, *p_h216, *p_o16, *p_gt16;
    __half *p_q16, *p_k16, *p_v16;
    __half *p_wqkv, *p_wo, *p_wg, *p_wv2, *p_wp;

    cudaGetSymbolAddress((void**)&p_x1, g_x1);
    cudaGetSymbolAddress((void**)&p_hA16, g_hA16);
    cudaGetSymbolAddress((void**)&p_h216, g_h216);
    cudaGetSymbolAddress((void**)&p_o16,  g_o16);
    cudaGetSymbolAddress((void**)&p_gt16, g_gt16);
    cudaGetSymbolAddress((void**)&p_q16,  g_q16);
    cudaGetSymbolAddress((void**)&p_k16,  g_k16);
    cudaGetSymbolAddress((void**)&p_v16,  g_v16);
    cudaGetSymbolAddress((void**)&p_wqkv, g_wqkv);
    cudaGetSymbolAddress((void**)&p_wo,   g_wo);
    cudaGetSymbolAddress((void**)&p_wg,   g_wg);
    cudaGetSymbolAddress((void**)&p_wv2,  g_wv2);
    cudaGetSymbolAddress((void**)&p_wp,   g_wp);

    cudaFuncSetAttribute(gemm_mma<1>, cudaFuncAttributeMaxDynamicSharedMemorySize, GM_SMEM);
    cudaFuncSetAttribute(gemm_qkv,   cudaFuncAttributeMaxDynamicSharedMemorySize, GM_SMEM);
    cudaFuncSetAttribute(gemm_ffn,   cudaFuncAttributeMaxDynamicSharedMemorySize, GM_SMEM);
    cudaFuncSetAttribute(flash_mma,  cudaFuncAttributeMaxDynamicSharedMemorySize, F_SMEM);

    // ---- weight conversion + transpose ----
    weight_conv4<<<dim3(64, 16, 4), 256>>>(
        wq, wk, wv, wo,
        p_wqkv, p_wqkv + DIM * DIM, p_wqkv + 2 * DIM * DIM, p_wo, DIM, DIM);
    weight_conv2<<<dim3(64, 64, 2), 256>>>(w_gate, w_val, p_wg, p_wv2, FF_DIM, DIM);
    weight_conv1<<<dim3(256, 16), 256>>>(w_proj, p_wp, DIM, FF_DIM);

    // ---- attention block ----
    rmsnorm_h<<<ROWS, 256>>>(x, attn_norm_w, p_hA16);
    gemm_qkv<<<dim3(24, 32), 256, GM_SMEM>>>(
        p_hA16, p_wqkv, bq, bk, bv, fcos, fsin,
        out_k, out_v, p_q16, p_k16, p_v16);

    copy_cache2<<<dim3(4096, 1, 2), 256>>>(k_cache, v_cache, out_k, out_v, p_k16, p_v16);

    flash_mma<<<dim3(S_LEN / FBM, BATCH * HEADS), 256, F_SMEM>>>(
        p_q16, p_k16, p_v16, p_o16);

    gemm_mma<1><<<dim3(8, 32), 256, GM_SMEM>>>(
        p_o16, p_wo, bo, x, p_x1, nullptr, ROWS, DIM, DIM);

    // ---- ffn block ----
    rmsnorm_h<<<ROWS, 256>>>(p_x1, ffn_norm_w, p_h216);
    gemm_ffn<<<dim3(64, 32), 256, GM_SMEM>>>(
        p_h216, p_wg, p_wv2, b_gate, b_val, p_gt16);
    gemm_mma<1><<<dim3(8, 32), 256, GM_SMEM>>>(
        p_gt16, p_wp, b_proj, p_x1, out_x, nullptr, ROWS, DIM, FF_DIM);
}

// round 12
// speedup vs baseline: 1.1197x; 1.1197x over previous
#include <cuda_runtime.h>
#include <cuda_bf16.h>
#include <cuda_fp16.h>
#include <cstdint>

// ---------------- problem constants ----------------
#define BATCH 2
#define S_LEN 2048
#define PREV_LEN 1024
#define T_LEN 3072
#define DIM 2048
#define HEADS 16
#define HD 128
#define FF_DIM 8192
#define ROWS (BATCH * S_LEN)  // 4096
#define QK_SCALE 0.08838834764831845f

#define OUT_X_ELEMS  (BATCH * S_LEN * DIM)
#define OUT_KV_ELEMS (BATCH * HEADS * T_LEN * HD)

// ================= PTX helpers (portable sm_80+) ====
__device__ __forceinline__ uint32_t smem_u32(const void* p) {
    uint32_t a;
    asm("{ .reg .u64 t; cvta.to.shared.u64 t, %1; cvt.u32.u64 %0, t; }" : "=r"(a) : "l"(p));
    return a;
}
__device__ __forceinline__ void cp_async16(uint32_t smem, const void* g) {
    asm volatile("cp.async.cg.shared.global [%0], [%1], 16;" :: "r"(smem), "l"(g) : "memory");
}
#define CP_COMMIT() asm volatile("cp.async.commit_group;" ::: "memory")
#define CP_WAIT6()  asm volatile("cp.async.wait_group 6;" ::: "memory")
#define CP_WAIT1()  asm volatile("cp.async.wait_group 1;" ::: "memory")

__device__ __forceinline__ void ldsm4(uint32_t* r, uint32_t addr) {
    asm volatile("ldmatrix.sync.aligned.m8n8.x4.shared.b16 {%0,%1,%2,%3}, [%4];"
        : "=r"(r[0]), "=r"(r[1]), "=r"(r[2]), "=r"(r[3]) : "r"(addr));
}
__device__ __forceinline__ void ldsm4t(uint32_t* r, uint32_t addr) {
    asm volatile("ldmatrix.sync.aligned.m8n8.x4.trans.shared.b16 {%0,%1,%2,%3}, [%4];"
        : "=r"(r[0]), "=r"(r[1]), "=r"(r[2]), "=r"(r[3]) : "r"(addr));
}
__device__ __forceinline__ void mma_f16(float* c, const uint32_t* a, uint32_t b0, uint32_t b1) {
    asm volatile(
        "mma.sync.aligned.m16n8k16.row.col.f32.f16.f16.f32 "
        "{%0,%1,%2,%3}, {%4,%5,%6,%7}, {%8,%9}, {%0,%1,%2,%3};"
        : "+f"(c[0]), "+f"(c[1]), "+f"(c[2]), "+f"(c[3])
        : "r"(a[0]), "r"(a[1]), "r"(a[2]), "r"(a[3]), "r"(b0), "r"(b1));
}
__device__ __forceinline__ uint32_t pack_f16(float a, float b) {
    __half2 t = __floats2half2_rn(a, b);
    return *(uint32_t*)&t;
}

// ---------------- scratch (device globals) --------
__device__ float g_x1 [ROWS * DIM];
__device__ __half g_hA16 [ROWS * DIM];
__device__ __half g_h216 [ROWS * DIM];
__device__ __half g_o16  [ROWS * DIM];
__device__ __half g_gt16 [ROWS * FF_DIM];
__device__ __half g_q16 [ROWS * DIM];
__device__ __half g_k16 [OUT_KV_ELEMS];
__device__ __half g_v16 [OUT_KV_ELEMS];
__device__ __half g_wqkv[3 * DIM * DIM];
__device__ __half g_wo  [DIM * DIM];
__device__ __half g_wg  [DIM * FF_DIM];
__device__ __half g_wv2 [DIM * FF_DIM];
__device__ __half g_wp  [FF_DIM * DIM];

// =====================================================================
// Weight converter + transpose: W[K][N] fp32 -> Wt[N][K] fp16.
// =====================================================================
__device__ __forceinline__ void wconv_body(
    const float* __restrict__ W, __half* __restrict__ T16, int N, int K)
{
    __shared__ float tile[32][133];
    const int k0 = blockIdx.x * 32, n0 = blockIdx.y * 128;
    const int tid = threadIdx.x;
    {
        const int kr = tid >> 3;
        const int nq = (tid & 7) * 16;
        const float* src = W + (size_t)(k0 + kr) * N + n0 + nq;
        #pragma unroll
        for (int u = 0; u < 4; u++) {
            float4 v = *(const float4*)(src + u * 4);
            tile[kr][nq + u * 4 + 0] = v.x;
            tile[kr][nq + u * 4 + 1] = v.y;
            tile[kr][nq + u * 4 + 2] = v.z;
            tile[kr][nq + u * 4 + 3] = v.w;
        }
    }
    __syncthreads();
    const int n = tid >> 1;
    const int q = tid & 1;
    __align__(16) __half hv[16];
    #pragma unroll
    for (int u = 0; u < 16; u++)
        hv[u] = __float2half(tile[q * 16 + u][n]);
    const size_t off = (size_t)(n0 + n) * K + k0 + q * 16;
    *(uint4*)(T16 + off)     = *(const uint4*)(hv);
    *(uint4*)(T16 + off + 8) = *(const uint4*)(hv + 8);
}

__global__ __launch_bounds__(256) void weight_conv1(
    const float* __restrict__ W, __half* __restrict__ T, int N, int K)
{
    wconv_body(W, T, N, K);
}
__global__ __launch_bounds__(256) void weight_conv2(
    const float* __restrict__ W0, const float* __restrict__ W1,
    __half* __restrict__ T0, __half* __restrict__ T1, int N, int K)
{
    const float* W = blockIdx.z ? W1 : W0;
    __half* T = blockIdx.z ? T1 : T0;
    wconv_body(W, T, N, K);
}
__global__ __launch_bounds__(256) void weight_conv4(
    const float* __restrict__ W0, const float* __restrict__ W1,
    const float* __restrict__ W2, const float* __restrict__ W3,
    __half* __restrict__ T0, __half* __restrict__ T1,
    __half* __restrict__ T2, __half* __restrict__ T3, int N, int K)
{
    const int z = blockIdx.z;
    const float* W = (z == 0) ? W0 : (z == 1) ? W1 : (z == 2) ? W2 : W3;
    __half* T = (z == 0) ? T0 : (z == 1) ? T1 : (z == 2) ? T2 : T3;
    wconv_body(W, T, N, K);
}

// =====================================================================
// rmsnorm -> single fp16 row-major
// =====================================================================
__global__ __launch_bounds__(256) void rmsnorm_h(
    const float* __restrict__ x, const float* __restrict__ w,
    __half* __restrict__ O16)
{
    __shared__ float red[256];
    const int tid = threadIdx.x;
    const int m = blockIdx.x;
    const float* xp = x + (size_t)m * DIM + tid * 8;
    float4 a = *(const float4*)xp;
    float4 b = *(const float4*)(xp + 4);
    float s = a.x*a.x + a.y*a.y + a.z*a.z + a.w*a.w
            + b.x*b.x + b.y*b.y + b.z*b.z + b.w*b.w;
    red[tid] = s;
    __syncthreads();
    #pragma unroll
    for (int off = 128; off > 0; off >>= 1) {
        if (tid < off) red[tid] += red[tid + off];
        __syncthreads();
    }
    float scale = rsqrtf(red[0] * (1.0f / DIM) + 1e-6f);
    const float* wp = w + tid * 8;
    float4 wa = *(const float4*)wp;
    float4 wb = *(const float4*)(wp + 4);
    float y[8];
    y[0] = a.x*scale*wa.x; y[1] = a.y*scale*wa.y; y[2] = a.z*scale*wa.z; y[3] = a.w*scale*wa.w;
    y[4] = b.x*scale*wb.x; y[5] = b.y*scale*wb.y; y[6] = b.z*scale*wb.z; y[7] = b.w*scale*wb.w;
    __align__(16) __half hv[8];
    #pragma unroll
    for (int j = 0; j < 8; j++) hv[j] = __float2half(y[j]);
    *(uint4*)(O16 + (size_t)m * DIM + tid * 8) = *(const uint4*)hv;
}

// =====================================================================
// fp16 single-pass GEMM core (R10 proven config). CTA 128x256,
// warp 64x64, 8 warps, K-chunk 32, 8-stage cp.async, single barrier.
// =====================================================================
#define GM_STAGES 8
#define GM_STAGE_BYTES 24576
#define GM_SMEM (GM_STAGES * GM_STAGE_BYTES)   // 196608
#define OFF_A 0
#define OFF_B 8192

__device__ __forceinline__ uint32_t swz(int r, int g) {
    return (uint32_t)(r * 64 + ((g ^ ((r >> 1) & 3)) << 4));
}

template<typename IssueF>
__device__ __forceinline__ void gemm_mainloop(
    float (&acc)[4][8][4], uint32_t sb, int nk, int wm, int wn, int lane,
    IssueF issue_stage)
{
    #pragma unroll
    for (int p = 0; p < 7; p++) { issue_stage(p, p); CP_COMMIT(); }

    for (int kc = 0; kc < nk; kc++) {
        CP_WAIT6();
        __syncthreads();
        if (kc + 7 < nk) issue_stage(kc + 7, (kc + 7) & 7);
        CP_COMMIT();

        const uint32_t st = sb + (kc & 7) * GM_STAGE_BYTES;
        #pragma unroll
        for (int h = 0; h < 2; h++) {
            uint32_t a[4][4];
            #pragma unroll
            for (int mi = 0; mi < 4; mi++) {
                const int r = wm * 64 + mi * 16 + (lane & 15);
                ldsm4(a[mi], st + OFF_A + swz(r, h * 2 + (lane >> 4)));
            }
            #pragma unroll
            for (int ng = 0; ng < 4; ng++) {
                uint32_t b[4];
                const int r = wn * 64 + ng * 16 + (lane & 15);
                ldsm4(b, st + OFF_B + swz(r, h * 2 + (lane >> 4)));
                #pragma unroll
                for (int mi = 0; mi < 4; mi++) {
                    mma_f16(acc[mi][ng * 2 + 0], a[mi], b[0], b[2]);
                    mma_f16(acc[mi][ng * 2 + 1], a[mi], b[1], b[3]);
                }
            }
        }
        // no trailing sync: next iteration's issue targets the slot whose
        // reads completed before this iteration's top barrier.
    }
}

#define GEMM_ISSUE_LAMBDA(A16, B16, m0, n0, K)                                  \
    auto issue_stage = [&](int kc, int slot) {                                  \
        const uint32_t st = sb + slot * GM_STAGE_BYTES;                         \
        const int kelem = kc * 32 + lg * 8;                                     \
        _Pragma("unroll")                                                       \
        for (int i = 0; i < 2; i++) {                                           \
            const int r = lr + i * 64;                                          \
            cp_async16(st + OFF_A + swz(r, lg), A16 + (size_t)(m0 + r) * K + kelem); \
        }                                                                       \
        _Pragma("unroll")                                                       \
        for (int i = 0; i < 4; i++) {                                           \
            const int r = lr + i * 64;                                          \
            cp_async16(st + OFF_B + swz(r, lg), B16 + (size_t)(n0 + r) * K + kelem); \
        }                                                                       \
    };

// =====================================================================
// Generic GEMM (MODE 1): C = A@B + bias + extra (fp32 out)
// =====================================================================
template<int MODE>
__global__ void __launch_bounds__(256, 1) gemm_mma(
    const __half* __restrict__ A16, const __half* __restrict__ B16,
    const float* __restrict__ bias, const float* __restrict__ extra,
    float* __restrict__ C, __half* __restrict__ C16,
    int M, int N, int K)
{
    extern __shared__ char smraw[];
    const uint32_t sb = smem_u32(smraw);
    const int tid = threadIdx.x;
    const int wid = tid >> 5;
    const int lane = tid & 31;
    const int wm = wid & 1;
    const int wn = wid >> 1;
    const int m0 = blockIdx.y * 128;
    const int n0 = blockIdx.x * 256;
    const int nk = K >> 5;
    const int lr = tid >> 2;
    const int lg = tid & 3;

    float acc[4][8][4];
    #pragma unroll
    for (int a = 0; a < 4; a++)
        #pragma unroll
        for (int b = 0; b < 8; b++)
            #pragma unroll
            for (int c = 0; c < 4; c++) acc[a][b][c] = 0.f;

    GEMM_ISSUE_LAMBDA(A16, B16, m0, n0, K)
    gemm_mainloop(acc, sb, nk, wm, wn, lane, issue_stage);

    const int mb = m0 + wm * 64;
    const int nb = n0 + wn * 64;
    #pragma unroll
    for (int mi = 0; mi < 4; mi++) {
        #pragma unroll
        for (int j = 0; j < 8; j++) {
            const int row = mb + mi * 16 + (lane >> 2);
            const int col = nb + j * 8 + (lane & 3) * 2;
            const float b0 = bias[col], b1 = bias[col + 1];
            #pragma unroll
            for (int half = 0; half < 2; half++) {
                const int rr = row + half * 8;
                float v0 = acc[mi][j][half * 2 + 0] + b0;
                float v1 = acc[mi][j][half * 2 + 1] + b1;
                if (MODE == 1) {
                    const float* ep = extra + (size_t)rr * N + col;
                    v0 += ep[0]; v1 += ep[1];
                }
                *(float2*)(C + (size_t)rr * N + col) = make_float2(v0, v1);
            }
        }
    }
}

// =====================================================================
// Fused QKV GEMM: B = concat[wq|wk|wv] (N=6144). Epilogue: RoPE+relayout.
// =====================================================================
__global__ void __launch_bounds__(256, 1) gemm_qkv(
    const __half* __restrict__ A16, const __half* __restrict__ B16,
    const float* __restrict__ bq, const float* __restrict__ bk, const float* __restrict__ bv,
    const float* __restrict__ cosb, const float* __restrict__ sinb,
    float* __restrict__ out_k, float* __restrict__ out_v,
    __half* __restrict__ Q16, __half* __restrict__ K16, __half* __restrict__ V16)
{
    extern __shared__ char smraw[];
    const uint32_t sb = smem_u32(smraw);
    const int tid = threadIdx.x;
    const int wid = tid >> 5;
    const int lane = tid & 31;
    const int wm = wid & 1;
    const int wn = wid >> 1;
    const int m0 = blockIdx.y * 128;
    const int n0 = blockIdx.x * 256;
    const int K = DIM;
    const int nk = K >> 5;
    const int lr = tid >> 2;
    const int lg = tid & 3;
    const int sec = n0 >> 11;
    const float* bias = (sec == 0) ? bq : ((sec == 1) ? bk : bv);

    float acc[4][8][4];
    #pragma unroll
    for (int a = 0; a < 4; a++)
        #pragma unroll
        for (int b = 0; b < 8; b++)
            #pragma unroll
            for (int c = 0; c < 4; c++) acc[a][b][c] = 0.f;

    GEMM_ISSUE_LAMBDA(A16, B16, m0, n0, K)
    gemm_mainloop(acc, sb, nk, wm, wn, lane, issue_stage);

    const int mb = m0 + wm * 64;
    const int nb = n0 + wn * 64;
    #pragma unroll
    for (int mi = 0; mi < 4; mi++) {
        #pragma unroll
        for (int j = 0; j < 8; j++) {
            const int row = mb + mi * 16 + (lane >> 2);
            const int col = nb + j * 8 + (lane & 3) * 2;
            const float b0 = bias[col & 2047], b1 = bias[(col & 2047) + 1];
            const int nc = col & 2047;
            const int h = nc >> 7;
            const int d = nc & 127;
            #pragma unroll
            for (int half = 0; half < 2; half++) {
                const int rr = row + half * 8;
                float v0 = acc[mi][j][half * 2 + 0] + b0;
                float v1 = acc[mi][j][half * 2 + 1] + b1;
                const int bi = rr >> 11;
                const int s = rr & 2047;
                if (sec < 2) {
                    const int i2 = d >> 1;
                    const float c = cosb[(PREV_LEN + s) * 64 + i2];
                    const float sn = sinb[(PREV_LEN + s) * 64 + i2];
                    const float r0 = v0 * c - v1 * sn;
                    const float r1 = v0 * sn + v1 * c;
                    if (sec == 0) {
                        *(__half2*)(Q16 + ((size_t)(bi * HEADS + h) * S_LEN + s) * HD + d) =
                            __floats2half2_rn(r0 * QK_SCALE, r1 * QK_SCALE);
                    } else {
                        const size_t off = ((size_t)(bi * HEADS + h) * T_LEN + PREV_LEN + s) * HD + d;
                        *(float2*)(out_k + off) = make_float2(r0, r1);
                        *(__half2*)(K16 + off) = __floats2half2_rn(r0, r1);
                    }
                } else {
                    const size_t off = ((size_t)(bi * HEADS + h) * T_LEN + PREV_LEN + s) * HD + d;
                    *(float2*)(out_v + off) = make_float2(v0, v1);
                    *(__half2*)(V16 + off) = __floats2half2_rn(v0, v1);
                }
            }
        }
    }
}

// =====================================================================
// Fused FFN gate+val GEMM: CTA 128(M)x128(N), K-chunk 32.
// stage: A 8K | Bg 8K | Bv 8K = 24KB, 8 stages.
// =====================================================================
#define FO_A  0
#define FO_BG 8192
#define FO_BV 16384

__global__ void __launch_bounds__(256, 1) gemm_ffn(
    const __half* __restrict__ A16,
    const __half* __restrict__ Bg, const __half* __restrict__ Bv,
    const float* __restrict__ bias_g, const float* __restrict__ bias_v,
    __half* __restrict__ C16)
{
    extern __shared__ char smraw[];
    const uint32_t sb = smem_u32(smraw);
    const int tid = threadIdx.x;
    const int wid = tid >> 5;
    const int lane = tid & 31;
    const int wm = wid & 1;
    const int wn = wid >> 1;
    const int m0 = blockIdx.y * 128;
    const int n0 = blockIdx.x * 128;
    const int K = DIM;
    const int nk = K >> 5;   // 64
    const int lr = tid >> 2;
    const int lg = tid & 3;

    float ag[4][4][4], av[4][4][4];
    #pragma unroll
    for (int a = 0; a < 4; a++)
        #pragma unroll
        for (int b = 0; b < 4; b++)
            #pragma unroll
            for (int c = 0; c < 4; c++) { ag[a][b][c] = 0.f; av[a][b][c] = 0.f; }

    auto issue_stage = [&](int kc, int slot) {
        const uint32_t st = sb + slot * GM_STAGE_BYTES;
        const int kelem = kc * 32 + lg * 8;
        #pragma unroll
        for (int i = 0; i < 2; i++) {
            const int r = lr + i * 64;
            const uint32_t sw = swz(r, lg);
            cp_async16(st + FO_A  + sw, A16 + (size_t)(m0 + r) * K + kelem);
            cp_async16(st + FO_BG + sw, Bg  + (size_t)(n0 + r) * K + kelem);
            cp_async16(st + FO_BV + sw, Bv  + (size_t)(n0 + r) * K + kelem);
        }
    };

    #pragma unroll
    for (int p = 0; p < 7; p++) { issue_stage(p, p); CP_COMMIT(); }

    for (int kc = 0; kc < nk; kc++) {
        CP_WAIT6();
        __syncthreads();
        if (kc + 7 < nk) issue_stage(kc + 7, (kc + 7) & 7);
        CP_COMMIT();

        const uint32_t st = sb + (kc & 7) * GM_STAGE_BYTES;
        #pragma unroll
        for (int h = 0; h < 2; h++) {
            uint32_t a[4][4];
            #pragma unroll
            for (int mi = 0; mi < 4; mi++) {
                const int r = wm * 64 + mi * 16 + (lane & 15);
                ldsm4(a[mi], st + FO_A + swz(r, h * 2 + (lane >> 4)));
            }
            #pragma unroll
            for (int ng = 0; ng < 2; ng++) {
                const int r = wn * 32 + ng * 16 + (lane & 15);
                const uint32_t sw = swz(r, h * 2 + (lane >> 4));
                uint32_t bg[4], bv[4];
                ldsm4(bg, st + FO_BG + sw);
                ldsm4(bv, st + FO_BV + sw);
                #pragma unroll
                for (int mi = 0; mi < 4; mi++) {
                    mma_f16(ag[mi][ng * 2 + 0], a[mi], bg[0], bg[2]);
                    mma_f16(ag[mi][ng * 2 + 1], a[mi], bg[1], bg[3]);
                    mma_f16(av[mi][ng * 2 + 0], a[mi], bv[0], bv[2]);
                    mma_f16(av[mi][ng * 2 + 1], a[mi], bv[1], bv[3]);
                }
            }
        }
    }

    const int mb = m0 + wm * 64;
    const int nb = n0 + wn * 32;
    #pragma unroll
    for (int mi = 0; mi < 4; mi++) {
        #pragma unroll
        for (int j = 0; j < 4; j++) {
            const int row = mb + mi * 16 + (lane >> 2);
            const int col = nb + j * 8 + (lane & 3) * 2;
            const float bg0 = bias_g[col], bg1 = bias_g[col + 1];
            const float bv0 = bias_v[col], bv1 = bias_v[col + 1];
            #pragma unroll
            for (int half = 0; half < 2; half++) {
                const int rr = row + half * 8;
                float gv0 = ag[mi][j][half * 2 + 0] + bg0;
                float gv1 = ag[mi][j][half * 2 + 1] + bg1;
                float vv0 = av[mi][j][half * 2 + 0] + bv0;
                float vv1 = av[mi][j][half * 2 + 1] + bv1;
                float o0 = gv0 / (1.f + __expf(-gv0)) * vv0;
                float o1 = gv1 / (1.f + __expf(-gv1)) * vv1;
                *(__half2*)(C16 + (size_t)rr * FF_DIM + col) = __floats2half2_rn(o0, o1);
            }
        }
    }
}

// ---------------- merged cache copy (z=0: K, z=1: V) ----------------
__global__ __launch_bounds__(256) void copy_cache2(
    const float* __restrict__ ink, const float* __restrict__ inv,
    float* __restrict__ outk, float* __restrict__ outv,
    __half* __restrict__ K16, __half* __restrict__ V16)
{
    const float* in = blockIdx.z ? inv : ink;
    float* out = blockIdx.z ? outv : outk;
    __half* H16 = blockIdx.z ? V16 : K16;
    int idx = blockIdx.x * 256 + threadIdx.x;   // 2^20 f4
    int bh  = idx >> 15;
    int rem = idx & 32767;
    float4 v = ((const float4*)in)[idx];
    size_t off4 = (size_t)bh * (T_LEN * HD / 4) + rem;
    ((float4*)out)[off4] = v;
    __align__(8) __half hv[4];
    hv[0] = __float2half(v.x); hv[1] = __float2half(v.y);
    hv[2] = __float2half(v.z); hv[3] = __float2half(v.w);
    *(uint2*)(H16 + off4 * 4) = *(const uint2*)hv;
}

// =====================================================================
// HMMA flash attention (R10 proven): fp16 1-pass QK, 3-stage KV,
// single barrier per tile.
// =====================================================================
#define FBM 128
#define FBN 64
#define F_OFF_Q  0
#define F_OFF_ST 32768
#define F_STAGE  32768
#define F_SMEM   (F_OFF_ST + 3 * F_STAGE)   // 131072

__device__ __forceinline__ uint32_t swz256(int r, int g) {
    return (uint32_t)((r << 8) + (((g ^ (r & 7)) & 15) << 4));
}

__global__ void __launch_bounds__(256) flash_mma(
    const __half* __restrict__ Q16, const __half* __restrict__ K16,
    const __half* __restrict__ V16, __half* __restrict__ O16)
{
    extern __shared__ char smraw[];
    const uint32_t sb = smem_u32(smraw);
    const int tid = threadIdx.x;
    const int wid = tid >> 5;
    const int lane = tid & 31;
    const int mtile = gridDim.x - 1 - blockIdx.x;
    const int bh = blockIdx.y;
    const int m0 = mtile * FBM;
    const int jend = (PREV_LEN + m0 + FBM) / FBN;
    const int mask_start = (PREV_LEN + m0) / FBN;

    {
        const size_t qo = ((size_t)bh * S_LEN + m0) * HD;
        for (int i = tid; i < 2048; i += 256) {
            int r = i >> 4, g = i & 15;
            cp_async16(sb + F_OFF_Q + swz256(r, g), Q16 + qo + (size_t)r * HD + g * 8);
        }
        CP_COMMIT();
    }

    auto issue_kv = [&](int jt, int slot) {
        const uint32_t st = sb + F_OFF_ST + slot * F_STAGE;
        const size_t ko = ((size_t)bh * T_LEN + jt * FBN) * HD;
        for (int i = tid; i < 1024; i += 256) {
            int r = i >> 4, g = i & 15;
            uint32_t sw = swz256(r, g);
            size_t go = ko + (size_t)r * HD + g * 8;
            cp_async16(st + sw, K16 + go);
            cp_async16(st + 16384 + sw, V16 + go);
        }
    };
    issue_kv(0, 0); CP_COMMIT();
    issue_kv(1, 1); CP_COMMIT();

    float of[16][4];
    #pragma unroll
    for (int i = 0; i < 16; i++)
        #pragma unroll
        for (int j = 0; j < 4; j++) of[i][j] = 0.f;
    float mrow0 = -1e30f, mrow1 = -1e30f, lrow0 = 0.f, lrow1 = 0.f;

    const int arow = wid * 16 + (lane & 15);
    const int agr  = lane >> 4;

    int slot = 0;
    int slot2 = 2;
    for (int jt = 0; jt < jend; jt++) {
        CP_WAIT1();
        __syncthreads();
        if (jt + 2 < jend) issue_kv(jt + 2, slot2);
        CP_COMMIT();

        const uint32_t st = sb + F_OFF_ST + slot * F_STAGE;
        const int t0 = jt * FBN;

        float sf[8][4];
        #pragma unroll
        for (int i = 0; i < 8; i++)
            #pragma unroll
            for (int j = 0; j < 4; j++) sf[i][j] = 0.f;

        #pragma unroll
        for (int kt = 0; kt < 8; kt++) {
            uint32_t a[4];
            ldsm4(a, sb + F_OFF_Q + swz256(arow, kt * 2 + agr));
            #pragma unroll
            for (int nb = 0; nb < 4; nb++) {
                uint32_t b[4];
                ldsm4(b, st + swz256(nb * 16 + (lane & 15), kt * 2 + agr));
                mma_f16(sf[nb * 2 + 0], a, b[0], b[2]);
                mma_f16(sf[nb * 2 + 1], a, b[1], b[3]);
            }
        }

        if (jt >= mask_start) {
            const int rb = m0 + wid * 16 + (lane >> 2);
            const int cb = t0 + (lane & 3) * 2;
            #pragma unroll
            for (int nt = 0; nt < 8; nt++) {
                const int c0 = cb + nt * 8;
                if (c0     > PREV_LEN + rb)     sf[nt][0] = -1e30f;
                if (c0 + 1 > PREV_LEN + rb)     sf[nt][1] = -1e30f;
                if (c0     > PREV_LEN + rb + 8) sf[nt][2] = -1e30f;
                if (c0 + 1 > PREV_LEN + rb + 8) sf[nt][3] = -1e30f;
            }
        }

        float mx0 = -1e30f, mx1 = -1e30f;
        #pragma unroll
        for (int nt = 0; nt < 8; nt++) {
            mx0 = fmaxf(mx0, fmaxf(sf[nt][0], sf[nt][1]));
            mx1 = fmaxf(mx1, fmaxf(sf[nt][2], sf[nt][3]));
        }
        mx0 = fmaxf(mx0, __shfl_xor_sync(0xFFFFFFFF, mx0, 1));
        mx0 = fmaxf(mx0, __shfl_xor_sync(0xFFFFFFFF, mx0, 2));
        mx1 = fmaxf(mx1, __shfl_xor_sync(0xFFFFFFFF, mx1, 1));
        mx1 = fmaxf(mx1, __shfl_xor_sync(0xFFFFFFFF, mx1, 2));
        const float nm0 = fmaxf(mrow0, mx0);
        const float nm1 = fmaxf(mrow1, mx1);
        const float al0 = __expf(mrow0 - nm0);
        const float al1 = __expf(mrow1 - nm1);
        mrow0 = nm0; mrow1 = nm1;

        float rs0 = 0.f, rs1 = 0.f;
        #pragma unroll
        for (int nt = 0; nt < 8; nt++) {
            sf[nt][0] = __expf(sf[nt][0] - nm0);
            sf[nt][1] = __expf(sf[nt][1] - nm0);
            sf[nt][2] = __expf(sf[nt][2] - nm1);
            sf[nt][3] = __expf(sf[nt][3] - nm1);
            rs0 += sf[nt][0] + sf[nt][1];
            rs1 += sf[nt][2] + sf[nt][3];
        }
        rs0 += __shfl_xor_sync(0xFFFFFFFF, rs0, 1);
        rs0 += __shfl_xor_sync(0xFFFFFFFF, rs0, 2);
        rs1 += __shfl_xor_sync(0xFFFFFFFF, rs1, 1);
        rs1 += __shfl_xor_sync(0xFFFFFFFF, rs1, 2);
        lrow0 = lrow0 * al0 + rs0;
        lrow1 = lrow1 * al1 + rs1;

        #pragma unroll
        for (int nt = 0; nt < 16; nt++) {
            of[nt][0] *= al0; of[nt][1] *= al0;
            of[nt][2] *= al1; of[nt][3] *= al1;
        }

        #pragma unroll
        for (int kt = 0; kt < 4; kt++) {
            uint32_t a[4];
            a[0] = pack_f16(sf[2 * kt][0],     sf[2 * kt][1]);
            a[1] = pack_f16(sf[2 * kt][2],     sf[2 * kt][3]);
            a[2] = pack_f16(sf[2 * kt + 1][0], sf[2 * kt + 1][1]);
            a[3] = pack_f16(sf[2 * kt + 1][2], sf[2 * kt + 1][3]);
            const int vrow = kt * 16 + ((lane >> 3) & 1) * 8 + (lane & 7);
            #pragma unroll
            for (int nb = 0; nb < 8; nb++) {
                uint32_t b[4];
                ldsm4t(b, st + 16384 + swz256(vrow, nb * 2 + ((lane >> 4) & 1)));
                mma_f16(of[nb * 2 + 0], a, b[0], b[1]);
                mma_f16(of[nb * 2 + 1], a, b[2], b[3]);
            }
        }
        slot  = (slot  == 2) ? 0 : slot + 1;
        slot2 = (slot2 == 2) ? 0 : slot2 + 1;
    }

    const float inv0 = 1.f / lrow0;
    const float inv1 = 1.f / lrow1;
    const int b = bh >> 4, h = bh & 15;
    const int r0 = m0 + wid * 16 + (lane >> 2);
    #pragma unroll
    for (int nt = 0; nt < 16; nt++) {
        const int gc = h * HD + nt * 8 + (lane & 3) * 2;
        *(__half2*)(O16 + (size_t)(b * S_LEN + r0) * DIM + gc) =
            __floats2half2_rn(of[nt][0] * inv0, of[nt][1] * inv0);
        *(__half2*)(O16 + (size_t)(b * S_LEN + r0 + 8) * DIM + gc) =
            __floats2half2_rn(of[nt][2] * inv1, of[nt][3] * inv1);
    }
}

// ---------------- launch ----------------
extern "C" void kernel_launch(void* const* d_in, const int* in_sizes, int n_in,
                              void* d_out, int out_size)
{
    const float* x          = (const float*)d_in[0];
    const float* k_cache    = (const float*)d_in[1];
    const float* v_cache    = (const float*)d_in[2];
    const float* attn_norm_w= (const float*)d_in[3];
    const float* ffn_norm_w = (const float*)d_in[4];
    const float* wq = (const float*)d_in[5];
    const float* bq = (const float*)d_in[6];
    const float* wk = (const float*)d_in[7];
    const float* bk = (const float*)d_in[8];
    const float* wv = (const float*)d_in[9];
    const float* bv = (const float*)d_in[10];
    const float* wo = (const float*)d_in[11];
    const float* bo = (const float*)d_in[12];
    const float* w_gate = (const float*)d_in[13];
    const float* b_gate = (const float*)d_in[14];
    const float* w_val  = (const float*)d_in[15];
    const float* b_val  = (const float*)d_in[16];
    const float* w_proj = (const float*)d_in[17];
    const float* b_proj = (const float*)d_in[18];
    const float* fcos   = (const float*)d_in[19];
    const float* fsin   = (const float*)d_in[20];

    float* out_x = (float*)d_out;
    float* out_k = out_x + OUT_X_ELEMS;
    float* out_v = out_k + OUT_KV_ELEMS;

    float *p_x1;
    __half *p_hA16, *p_h216, *p_o16, *p_gt16;
    __half *p_q16, *p_k16, *p_v16;
    __half *p_wqkv, *p_wo, *p_wg, *p_wv2, *p_wp;

    cudaGetSymbolAddress((void**)&p_x1, g_x1);
    cudaGetSymbolAddress((void**)&p_hA16, g_hA16);
    cudaGetSymbolAddress((void**)&p_h216, g_h216);
    cudaGetSymbolAddress((void**)&p_o16,  g_o16);
    cudaGetSymbolAddress((void**)&p_gt16, g_gt16);
    cudaGetSymbolAddress((void**)&p_q16,  g_q16);
    cudaGetSymbolAddress((void**)&p_k16,  g_k16);
    cudaGetSymbolAddress((void**)&p_v16,  g_v16);
    cudaGetSymbolAddress((void**)&p_wqkv, g_wqkv);
    cudaGetSymbolAddress((void**)&p_wo,   g_wo);
    cudaGetSymbolAddress((void**)&p_wg,   g_wg);
    cudaGetSymbolAddress((void**)&p_wv2,  g_wv2);
    cudaGetSymbolAddress((void**)&p_wp,   g_wp);

    cudaFuncSetAttribute(gemm_mma<1>, cudaFuncAttributeMaxDynamicSharedMemorySize, GM_SMEM);
    cudaFuncSetAttribute(gemm_qkv,   cudaFuncAttributeMaxDynamicSharedMemorySize, GM_SMEM);
    cudaFuncSetAttribute(gemm_ffn,   cudaFuncAttributeMaxDynamicSharedMemorySize, GM_SMEM);
    cudaFuncSetAttribute(flash_mma,  cudaFuncAttributeMaxDynamicSharedMemorySize, F_SMEM);

    // ---- weight conversion + transpose ----
    weight_conv4<<<dim3(64, 16, 4), 256>>>(
        wq, wk, wv, wo,
        p_wqkv, p_wqkv + DIM * DIM, p_wqkv + 2 * DIM * DIM, p_wo, DIM, DIM);
    weight_conv2<<<dim3(64, 64, 2), 256>>>(w_gate, w_val, p_wg, p_wv2, FF_DIM, DIM);
    weight_conv1<<<dim3(256, 16), 256>>>(w_proj, p_wp, DIM, FF_DIM);

    // ---- attention block ----
    rmsnorm_h<<<ROWS, 256>>>(x, attn_norm_w, p_hA16);
    gemm_qkv<<<dim3(24, 32), 256, GM_SMEM>>>(
        p_hA16, p_wqkv, bq, bk, bv, fcos, fsin,
        out_k, out_v, p_q16, p_k16, p_v16);

    copy_cache2<<<dim3(4096, 1, 2), 256>>>(k_cache, v_cache, out_k, out_v, p_k16, p_v16);

    flash_mma<<<dim3(S_LEN / FBM, BATCH * HEADS), 256, F_SMEM>>>(
        p_q16, p_k16, p_v16, p_o16);

    gemm_mma<1><<<dim3(8, 32), 256, GM_SMEM>>>(
        p_o16, p_wo, bo, x, p_x1, nullptr, ROWS, DIM, DIM);

    // ---- ffn block ----
    rmsnorm_h<<<ROWS, 256>>>(p_x1, ffn_norm_w, p_h216);
    gemm_ffn<<<dim3(64, 32), 256, GM_SMEM>>>(
        p_h216, p_wg, p_wv2, b_gate, b_val, p_gt16);
    gemm_mma<1><<<dim3(8, 32), 256, GM_SMEM>>>(
        p_gt16, p_wp, b_proj, p_x1, out_x, nullptr, ROWS, DIM, FF_DIM);
}

// round 13
// speedup vs baseline: 1.1248x; 1.0046x over previous
#include <cuda_runtime.h>
#include <cuda_bf16.h>
#include <cuda_fp16.h>
#include <cstdint>

// ---------------- problem constants ----------------
#define BATCH 2
#define S_LEN 2048
#define PREV_LEN 1024
#define T_LEN 3072
#define DIM 2048
#define HEADS 16
#define HD 128
#define FF_DIM 8192
#define ROWS (BATCH * S_LEN)  // 4096
#define QK_SCALE 0.08838834764831845f

#define OUT_X_ELEMS  (BATCH * S_LEN * DIM)
#define OUT_KV_ELEMS (BATCH * HEADS * T_LEN * HD)

// ================= PTX helpers (portable sm_80+) ====
__device__ __forceinline__ uint32_t smem_u32(const void* p) {
    uint32_t a;
    asm("{ .reg .u64 t; cvta.to.shared.u64 t, %1; cvt.u32.u64 %0, t; }" : "=r"(a) : "l"(p));
    return a;
}
__device__ __forceinline__ void cp_async16(uint32_t smem, const void* g) {
    asm volatile("cp.async.cg.shared.global [%0], [%1], 16;" :: "r"(smem), "l"(g) : "memory");
}
#define CP_COMMIT() asm volatile("cp.async.commit_group;" ::: "memory")
#define CP_WAIT6()  asm volatile("cp.async.wait_group 6;" ::: "memory")
#define CP_WAIT1()  asm volatile("cp.async.wait_group 1;" ::: "memory")

__device__ __forceinline__ void ldsm4(uint32_t* r, uint32_t addr) {
    asm volatile("ldmatrix.sync.aligned.m8n8.x4.shared.b16 {%0,%1,%2,%3}, [%4];"
        : "=r"(r[0]), "=r"(r[1]), "=r"(r[2]), "=r"(r[3]) : "r"(addr));
}
__device__ __forceinline__ void ldsm4t(uint32_t* r, uint32_t addr) {
    asm volatile("ldmatrix.sync.aligned.m8n8.x4.trans.shared.b16 {%0,%1,%2,%3}, [%4];"
        : "=r"(r[0]), "=r"(r[1]), "=r"(r[2]), "=r"(r[3]) : "r"(addr));
}
__device__ __forceinline__ void mma_f16(float* c, const uint32_t* a, uint32_t b0, uint32_t b1) {
    asm volatile(
        "mma.sync.aligned.m16n8k16.row.col.f32.f16.f16.f32 "
        "{%0,%1,%2,%3}, {%4,%5,%6,%7}, {%8,%9}, {%0,%1,%2,%3};"
        : "+f"(c[0]), "+f"(c[1]), "+f"(c[2]), "+f"(c[3])
        : "r"(a[0]), "r"(a[1]), "r"(a[2]), "r"(a[3]), "r"(b0), "r"(b1));
}
__device__ __forceinline__ uint32_t pack_f16(float a, float b) {
    __half2 t = __floats2half2_rn(a, b);
    return *(uint32_t*)&t;
}

// ---------------- scratch (device globals) --------
__device__ float g_x1 [ROWS * DIM];
__device__ __half g_hA16 [ROWS * DIM];
__device__ __half g_h216 [ROWS * DIM];
__device__ __half g_o16  [ROWS * DIM];
__device__ __half g_gt16 [ROWS * FF_DIM];
__device__ __half g_q16 [ROWS * DIM];
__device__ __half g_k16 [OUT_KV_ELEMS];
__device__ __half g_v16 [OUT_KV_ELEMS];
__device__ __half g_wqkv[3 * DIM * DIM];
__device__ __half g_wo  [DIM * DIM];
__device__ __half g_wg  [DIM * FF_DIM];
__device__ __half g_wv2 [DIM * FF_DIM];
__device__ __half g_wp  [FF_DIM * DIM];

// =====================================================================
// prep kernel: 1-D grid.
//   bid < 4096           : rmsnorm(x, attn_norm_w) -> hA16 (row = bid)
//   bid >= 4096 (16384)  : weight conversion tile (decode table)
// =====================================================================
__global__ __launch_bounds__(256) void prep_kernel(
    const float* __restrict__ x, const float* __restrict__ anw,
    __half* __restrict__ hA,
    const float* __restrict__ wq, const float* __restrict__ wk,
    const float* __restrict__ wv, const float* __restrict__ wo,
    const float* __restrict__ wg, const float* __restrict__ wv2,
    const float* __restrict__ wp,
    __half* __restrict__ Tqkv, __half* __restrict__ Two,
    __half* __restrict__ Twg, __half* __restrict__ Twv2,
    __half* __restrict__ Twp)
{
    __shared__ float sm[32 * 133];
    const int tid = threadIdx.x;
    const int bid = blockIdx.x;

    if (bid < ROWS) {
        // ---- rmsnorm row ----
        const float* xp = x + (size_t)bid * DIM + tid * 8;
        float4 a = *(const float4*)xp;
        float4 b = *(const float4*)(xp + 4);
        float s = a.x*a.x + a.y*a.y + a.z*a.z + a.w*a.w
                + b.x*b.x + b.y*b.y + b.z*b.z + b.w*b.w;
        sm[tid] = s;
        __syncthreads();
        #pragma unroll
        for (int off = 128; off > 0; off >>= 1) {
            if (tid < off) sm[tid] += sm[tid + off];
            __syncthreads();
        }
        float scale = rsqrtf(sm[0] * (1.0f / DIM) + 1e-6f);
        const float* wpt = anw + tid * 8;
        float4 wa = *(const float4*)wpt;
        float4 wb = *(const float4*)(wpt + 4);
        float y[8];
        y[0] = a.x*scale*wa.x; y[1] = a.y*scale*wa.y; y[2] = a.z*scale*wa.z; y[3] = a.w*scale*wa.w;
        y[4] = b.x*scale*wb.x; y[5] = b.y*scale*wb.y; y[6] = b.z*scale*wb.z; y[7] = b.w*scale*wb.w;
        __align__(16) __half hv[8];
        #pragma unroll
        for (int j = 0; j < 8; j++) hv[j] = __float2half(y[j]);
        *(uint4*)(hA + (size_t)bid * DIM + tid * 8) = *(const uint4*)hv;
        return;
    }

    // ---- weight conversion tile ----
    const int cid = bid - ROWS;
    const float* W; __half* T; int N, K, kb, nb;
    if (cid < 3072) {
        const int mat = cid / 1024, b = cid % 1024;
        W = (mat == 0) ? wq : ((mat == 1) ? wk : wv);
        T = Tqkv + (size_t)mat * DIM * DIM;
        N = DIM; K = DIM; kb = b % 64; nb = b / 64;
    } else if (cid < 4096) {
        const int b = cid - 3072;
        W = wo; T = Two; N = DIM; K = DIM; kb = b % 64; nb = b / 64;
    } else if (cid < 8192) {
        const int b = cid - 4096;
        W = wg; T = Twg; N = FF_DIM; K = DIM; kb = b % 64; nb = b / 64;
    } else if (cid < 12288) {
        const int b = cid - 8192;
        W = wv2; T = Twv2; N = FF_DIM; K = DIM; kb = b % 64; nb = b / 64;
    } else {
        const int b = cid - 12288;
        W = wp; T = Twp; N = DIM; K = FF_DIM; kb = b % 256; nb = b / 256;
    }
    const int k0 = kb * 32, n0 = nb * 128;
    {
        const int kr = tid >> 3;
        const int nq = (tid & 7) * 16;
        const float* src = W + (size_t)(k0 + kr) * N + n0 + nq;
        #pragma unroll
        for (int u = 0; u < 4; u++) {
            float4 v = *(const float4*)(src + u * 4);
            sm[kr * 133 + nq + u * 4 + 0] = v.x;
            sm[kr * 133 + nq + u * 4 + 1] = v.y;
            sm[kr * 133 + nq + u * 4 + 2] = v.z;
            sm[kr * 133 + nq + u * 4 + 3] = v.w;
        }
    }
    __syncthreads();
    const int n = tid >> 1;
    const int q = tid & 1;
    __align__(16) __half hv[16];
    #pragma unroll
    for (int u = 0; u < 16; u++)
        hv[u] = __float2half(sm[(q * 16 + u) * 133 + n]);
    const size_t off = (size_t)(n0 + n) * K + k0 + q * 16;
    *(uint4*)(T + off)     = *(const uint4*)(hv);
    *(uint4*)(T + off + 8) = *(const uint4*)(hv + 8);
}

// =====================================================================
// rmsnorm -> single fp16 row-major (ffn block)
// =====================================================================
__global__ __launch_bounds__(256) void rmsnorm_h(
    const float* __restrict__ x, const float* __restrict__ w,
    __half* __restrict__ O16)
{
    __shared__ float red[256];
    const int tid = threadIdx.x;
    const int m = blockIdx.x;
    const float* xp = x + (size_t)m * DIM + tid * 8;
    float4 a = *(const float4*)xp;
    float4 b = *(const float4*)(xp + 4);
    float s = a.x*a.x + a.y*a.y + a.z*a.z + a.w*a.w
            + b.x*b.x + b.y*b.y + b.z*b.z + b.w*b.w;
    red[tid] = s;
    __syncthreads();
    #pragma unroll
    for (int off = 128; off > 0; off >>= 1) {
        if (tid < off) red[tid] += red[tid + off];
        __syncthreads();
    }
    float scale = rsqrtf(red[0] * (1.0f / DIM) + 1e-6f);
    const float* wp = w + tid * 8;
    float4 wa = *(const float4*)wp;
    float4 wb = *(const float4*)(wp + 4);
    float y[8];
    y[0] = a.x*scale*wa.x; y[1] = a.y*scale*wa.y; y[2] = a.z*scale*wa.z; y[3] = a.w*scale*wa.w;
    y[4] = b.x*scale*wb.x; y[5] = b.y*scale*wb.y; y[6] = b.z*scale*wb.z; y[7] = b.w*scale*wb.w;
    __align__(16) __half hv[8];
    #pragma unroll
    for (int j = 0; j < 8; j++) hv[j] = __float2half(y[j]);
    *(uint4*)(O16 + (size_t)m * DIM + tid * 8) = *(const uint4*)hv;
}

// =====================================================================
// fp16 single-pass GEMM core (proven). CTA 128x256, warp 64x64, 8 warps,
// K-chunk 32, 8-stage cp.async, single barrier per chunk.
// =====================================================================
#define GM_STAGES 8
#define GM_STAGE_BYTES 24576
#define GM_SMEM (GM_STAGES * GM_STAGE_BYTES)   // 196608
#define OFF_A 0
#define OFF_B 8192

__device__ __forceinline__ uint32_t swz(int r, int g) {
    return (uint32_t)(r * 64 + ((g ^ ((r >> 1) & 3)) << 4));
}

template<typename IssueF>
__device__ __forceinline__ void gemm_mainloop(
    float (&acc)[4][8][4], uint32_t sb, int nk, int wm, int wn, int lane,
    IssueF issue_stage)
{
    #pragma unroll
    for (int p = 0; p < 7; p++) { issue_stage(p, p); CP_COMMIT(); }

    for (int kc = 0; kc < nk; kc++) {
        CP_WAIT6();
        __syncthreads();
        if (kc + 7 < nk) issue_stage(kc + 7, (kc + 7) & 7);
        CP_COMMIT();

        const uint32_t st = sb + (kc & 7) * GM_STAGE_BYTES;
        #pragma unroll
        for (int h = 0; h < 2; h++) {
            uint32_t a[4][4];
            #pragma unroll
            for (int mi = 0; mi < 4; mi++) {
                const int r = wm * 64 + mi * 16 + (lane & 15);
                ldsm4(a[mi], st + OFF_A + swz(r, h * 2 + (lane >> 4)));
            }
            #pragma unroll
            for (int ng = 0; ng < 4; ng++) {
                uint32_t b[4];
                const int r = wn * 64 + ng * 16 + (lane & 15);
                ldsm4(b, st + OFF_B + swz(r, h * 2 + (lane >> 4)));
                #pragma unroll
                for (int mi = 0; mi < 4; mi++) {
                    mma_f16(acc[mi][ng * 2 + 0], a[mi], b[0], b[2]);
                    mma_f16(acc[mi][ng * 2 + 1], a[mi], b[1], b[3]);
                }
            }
        }
        // no trailing sync: next iteration's issue targets the slot whose
        // reads completed before this iteration's top barrier.
    }
}

#define GEMM_ISSUE_LAMBDA(A16, B16, m0, n0, K)                                  \
    auto issue_stage = [&](int kc, int slot) {                                  \
        const uint32_t st = sb + slot * GM_STAGE_BYTES;                         \
        const int kelem = kc * 32 + lg * 8;                                     \
        _Pragma("unroll")                                                       \
        for (int i = 0; i < 2; i++) {                                           \
            const int r = lr + i * 64;                                          \
            cp_async16(st + OFF_A + swz(r, lg), A16 + (size_t)(m0 + r) * K + kelem); \
        }                                                                       \
        _Pragma("unroll")                                                       \
        for (int i = 0; i < 4; i++) {                                           \
            const int r = lr + i * 64;                                          \
            cp_async16(st + OFF_B + swz(r, lg), B16 + (size_t)(n0 + r) * K + kelem); \
        }                                                                       \
    };

// =====================================================================
// Generic GEMM (MODE 1): C = A@B + bias + extra (fp32 out)
// =====================================================================
template<int MODE>
__global__ void __launch_bounds__(256, 1) gemm_mma(
    const __half* __restrict__ A16, const __half* __restrict__ B16,
    const float* __restrict__ bias, const float* __restrict__ extra,
    float* __restrict__ C, __half* __restrict__ C16,
    int M, int N, int K)
{
    extern __shared__ char smraw[];
    const uint32_t sb = smem_u32(smraw);
    const int tid = threadIdx.x;
    const int wid = tid >> 5;
    const int lane = tid & 31;
    const int wm = wid & 1;
    const int wn = wid >> 1;
    const int m0 = blockIdx.y * 128;
    const int n0 = blockIdx.x * 256;
    const int nk = K >> 5;
    const int lr = tid >> 2;
    const int lg = tid & 3;

    float acc[4][8][4];
    #pragma unroll
    for (int a = 0; a < 4; a++)
        #pragma unroll
        for (int b = 0; b < 8; b++)
            #pragma unroll
            for (int c = 0; c < 4; c++) acc[a][b][c] = 0.f;

    GEMM_ISSUE_LAMBDA(A16, B16, m0, n0, K)
    gemm_mainloop(acc, sb, nk, wm, wn, lane, issue_stage);

    const int mb = m0 + wm * 64;
    const int nb = n0 + wn * 64;
    #pragma unroll
    for (int mi = 0; mi < 4; mi++) {
        #pragma unroll
        for (int j = 0; j < 8; j++) {
            const int row = mb + mi * 16 + (lane >> 2);
            const int col = nb + j * 8 + (lane & 3) * 2;
            const float b0 = bias[col], b1 = bias[col + 1];
            #pragma unroll
            for (int half = 0; half < 2; half++) {
                const int rr = row + half * 8;
                float v0 = acc[mi][j][half * 2 + 0] + b0;
                float v1 = acc[mi][j][half * 2 + 1] + b1;
                if (MODE == 1) {
                    const float* ep = extra + (size_t)rr * N + col;
                    v0 += ep[0]; v1 += ep[1];
                }
                *(float2*)(C + (size_t)rr * N + col) = make_float2(v0, v1);
            }
        }
    }
}

// =====================================================================
// Fused QKV GEMM + cache copy. B = concat[wq|wk|wv] (N=6144).
// grid (26, 32): blockIdx.x < 24 -> GEMM tile; else -> cache-copy CTA
// (64 copy CTAs grid-stride over 2^21 float4: z=0 K-cache, z=1 V-cache).
// GEMM epilogue: RoPE+relayout. Copy region (t<1024) is disjoint from
// GEMM writes (t>=1024); both done before flash launch.
// =====================================================================
__global__ void __launch_bounds__(256, 1) gemm_qkv(
    const __half* __restrict__ A16, const __half* __restrict__ B16,
    const float* __restrict__ bq, const float* __restrict__ bk, const float* __restrict__ bv,
    const float* __restrict__ cosb, const float* __restrict__ sinb,
    const float* __restrict__ k_cache, const float* __restrict__ v_cache,
    float* __restrict__ out_k, float* __restrict__ out_v,
    __half* __restrict__ Q16, __half* __restrict__ K16, __half* __restrict__ V16)
{
    extern __shared__ char smraw[];
    const int tid = threadIdx.x;

    if (blockIdx.x >= 24) {
        // ---- cache copy path ----
        const int cidx = (blockIdx.x - 24) * 32 + blockIdx.y;   // 0..63
        for (int idx = cidx * 256 + tid; idx < (1 << 21); idx += 64 * 256) {
            const int z = idx >> 20;
            const int i = idx & ((1 << 20) - 1);
            const float* in = z ? v_cache : k_cache;
            float* out = z ? out_v : out_k;
            __half* H16 = z ? V16 : K16;
            const int bh  = i >> 15;
            const int rem = i & 32767;
            float4 v = ((const float4*)in)[i];
            size_t off4 = (size_t)bh * (T_LEN * HD / 4) + rem;
            ((float4*)out)[off4] = v;
            __align__(8) __half hv[4];
            hv[0] = __float2half(v.x); hv[1] = __float2half(v.y);
            hv[2] = __float2half(v.z); hv[3] = __float2half(v.w);
            *(uint2*)(H16 + off4 * 4) = *(const uint2*)hv;
        }
        return;
    }

    const uint32_t sb = smem_u32(smraw);
    const int wid = tid >> 5;
    const int lane = tid & 31;
    const int wm = wid & 1;
    const int wn = wid >> 1;
    const int m0 = blockIdx.y * 128;
    const int n0 = blockIdx.x * 256;
    const int K = DIM;
    const int nk = K >> 5;
    const int lr = tid >> 2;
    const int lg = tid & 3;
    const int sec = n0 >> 11;
    const float* bias = (sec == 0) ? bq : ((sec == 1) ? bk : bv);

    float acc[4][8][4];
    #pragma unroll
    for (int a = 0; a < 4; a++)
        #pragma unroll
        for (int b = 0; b < 8; b++)
            #pragma unroll
            for (int c = 0; c < 4; c++) acc[a][b][c] = 0.f;

    GEMM_ISSUE_LAMBDA(A16, B16, m0, n0, K)
    gemm_mainloop(acc, sb, nk, wm, wn, lane, issue_stage);

    const int mb = m0 + wm * 64;
    const int nb = n0 + wn * 64;
    #pragma unroll
    for (int mi = 0; mi < 4; mi++) {
        #pragma unroll
        for (int j = 0; j < 8; j++) {
            const int row = mb + mi * 16 + (lane >> 2);
            const int col = nb + j * 8 + (lane & 3) * 2;
            const float b0 = bias[col & 2047], b1 = bias[(col & 2047) + 1];
            const int nc = col & 2047;
            const int h = nc >> 7;
            const int d = nc & 127;
            #pragma unroll
            for (int half = 0; half < 2; half++) {
                const int rr = row + half * 8;
                float v0 = acc[mi][j][half * 2 + 0] + b0;
                float v1 = acc[mi][j][half * 2 + 1] + b1;
                const int bi = rr >> 11;
                const int s = rr & 2047;
                if (sec < 2) {
                    const int i2 = d >> 1;
                    const float c = cosb[(PREV_LEN + s) * 64 + i2];
                    const float sn = sinb[(PREV_LEN + s) * 64 + i2];
                    const float r0 = v0 * c - v1 * sn;
                    const float r1 = v0 * sn + v1 * c;
                    if (sec == 0) {
                        *(__half2*)(Q16 + ((size_t)(bi * HEADS + h) * S_LEN + s) * HD + d) =
                            __floats2half2_rn(r0 * QK_SCALE, r1 * QK_SCALE);
                    } else {
                        const size_t off = ((size_t)(bi * HEADS + h) * T_LEN + PREV_LEN + s) * HD + d;
                        *(float2*)(out_k + off) = make_float2(r0, r1);
                        *(__half2*)(K16 + off) = __floats2half2_rn(r0, r1);
                    }
                } else {
                    const size_t off = ((size_t)(bi * HEADS + h) * T_LEN + PREV_LEN + s) * HD + d;
                    *(float2*)(out_v + off) = make_float2(v0, v1);
                    *(__half2*)(V16 + off) = __floats2half2_rn(v0, v1);
                }
            }
        }
    }
}

// =====================================================================
// Fused FFN gate+val GEMM: CTA 128(M)x128(N), K-chunk 32.
// stage: A 8K | Bg 8K | Bv 8K = 24KB, 8 stages.
// =====================================================================
#define FO_A  0
#define FO_BG 8192
#define FO_BV 16384

__global__ void __launch_bounds__(256, 1) gemm_ffn(
    const __half* __restrict__ A16,
    const __half* __restrict__ Bg, const __half* __restrict__ Bv,
    const float* __restrict__ bias_g, const float* __restrict__ bias_v,
    __half* __restrict__ C16)
{
    extern __shared__ char smraw[];
    const uint32_t sb = smem_u32(smraw);
    const int tid = threadIdx.x;
    const int wid = tid >> 5;
    const int lane = tid & 31;
    const int wm = wid & 1;
    const int wn = wid >> 1;
    const int m0 = blockIdx.y * 128;
    const int n0 = blockIdx.x * 128;
    const int K = DIM;
    const int nk = K >> 5;   // 64
    const int lr = tid >> 2;
    const int lg = tid & 3;

    float ag[4][4][4], av[4][4][4];
    #pragma unroll
    for (int a = 0; a < 4; a++)
        #pragma unroll
        for (int b = 0; b < 4; b++)
            #pragma unroll
            for (int c = 0; c < 4; c++) { ag[a][b][c] = 0.f; av[a][b][c] = 0.f; }

    auto issue_stage = [&](int kc, int slot) {
        const uint32_t st = sb + slot * GM_STAGE_BYTES;
        const int kelem = kc * 32 + lg * 8;
        #pragma unroll
        for (int i = 0; i < 2; i++) {
            const int r = lr + i * 64;
            const uint32_t sw = swz(r, lg);
            cp_async16(st + FO_A  + sw, A16 + (size_t)(m0 + r) * K + kelem);
            cp_async16(st + FO_BG + sw, Bg  + (size_t)(n0 + r) * K + kelem);
            cp_async16(st + FO_BV + sw, Bv  + (size_t)(n0 + r) * K + kelem);
        }
    };

    #pragma unroll
    for (int p = 0; p < 7; p++) { issue_stage(p, p); CP_COMMIT(); }

    for (int kc = 0; kc < nk; kc++) {
        CP_WAIT6();
        __syncthreads();
        if (kc + 7 < nk) issue_stage(kc + 7, (kc + 7) & 7);
        CP_COMMIT();

        const uint32_t st = sb + (kc & 7) * GM_STAGE_BYTES;
        #pragma unroll
        for (int h = 0; h < 2; h++) {
            uint32_t a[4][4];
            #pragma unroll
            for (int mi = 0; mi < 4; mi++) {
                const int r = wm * 64 + mi * 16 + (lane & 15);
                ldsm4(a[mi], st + FO_A + swz(r, h * 2 + (lane >> 4)));
            }
            #pragma unroll
            for (int ng = 0; ng < 2; ng++) {
                const int r = wn * 32 + ng * 16 + (lane & 15);
                const uint32_t sw = swz(r, h * 2 + (lane >> 4));
                uint32_t bg[4], bv[4];
                ldsm4(bg, st + FO_BG + sw);
                ldsm4(bv, st + FO_BV + sw);
                #pragma unroll
                for (int mi = 0; mi < 4; mi++) {
                    mma_f16(ag[mi][ng * 2 + 0], a[mi], bg[0], bg[2]);
                    mma_f16(ag[mi][ng * 2 + 1], a[mi], bg[1], bg[3]);
                    mma_f16(av[mi][ng * 2 + 0], a[mi], bv[0], bv[2]);
                    mma_f16(av[mi][ng * 2 + 1], a[mi], bv[1], bv[3]);
                }
            }
        }
    }

    const int mb = m0 + wm * 64;
    const int nb = n0 + wn * 32;
    #pragma unroll
    for (int mi = 0; mi < 4; mi++) {
        #pragma unroll
        for (int j = 0; j < 4; j++) {
            const int row = mb + mi * 16 + (lane >> 2);
            const int col = nb + j * 8 + (lane & 3) * 2;
            const float bg0 = bias_g[col], bg1 = bias_g[col + 1];
            const float bv0 = bias_v[col], bv1 = bias_v[col + 1];
            #pragma unroll
            for (int half = 0; half < 2; half++) {
                const int rr = row + half * 8;
                float gv0 = ag[mi][j][half * 2 + 0] + bg0;
                float gv1 = ag[mi][j][half * 2 + 1] + bg1;
                float vv0 = av[mi][j][half * 2 + 0] + bv0;
                float vv1 = av[mi][j][half * 2 + 1] + bv1;
                float o0 = gv0 / (1.f + __expf(-gv0)) * vv0;
                float o1 = gv1 / (1.f + __expf(-gv1)) * vv1;
                *(__half2*)(C16 + (size_t)rr * FF_DIM + col) = __floats2half2_rn(o0, o1);
            }
        }
    }
}

// =====================================================================
// HMMA flash attention (proven): fp16 1-pass QK, 3-stage KV,
// single barrier per tile.
// =====================================================================
#define FBM 128
#define FBN 64
#define F_OFF_Q  0
#define F_OFF_ST 32768
#define F_STAGE  32768
#define F_SMEM   (F_OFF_ST + 3 * F_STAGE)   // 131072

__device__ __forceinline__ uint32_t swz256(int r, int g) {
    return (uint32_t)((r << 8) + (((g ^ (r & 7)) & 15) << 4));
}

__global__ void __launch_bounds__(256) flash_mma(
    const __half* __restrict__ Q16, const __half* __restrict__ K16,
    const __half* __restrict__ V16, __half* __restrict__ O16)
{
    extern __shared__ char smraw[];
    const uint32_t sb = smem_u32(smraw);
    const int tid = threadIdx.x;
    const int wid = tid >> 5;
    const int lane = tid & 31;
    const int mtile = gridDim.x - 1 - blockIdx.x;
    const int bh = blockIdx.y;
    const int m0 = mtile * FBM;
    const int jend = (PREV_LEN + m0 + FBM) / FBN;
    const int mask_start = (PREV_LEN + m0) / FBN;

    {
        const size_t qo = ((size_t)bh * S_LEN + m0) * HD;
        for (int i = tid; i < 2048; i += 256) {
            int r = i >> 4, g = i & 15;
            cp_async16(sb + F_OFF_Q + swz256(r, g), Q16 + qo + (size_t)r * HD + g * 8);
        }
        CP_COMMIT();
    }

    auto issue_kv = [&](int jt, int slot) {
        const uint32_t st = sb + F_OFF_ST + slot * F_STAGE;
        const size_t ko = ((size_t)bh * T_LEN + jt * FBN) * HD;
        for (int i = tid; i < 1024; i += 256) {
            int r = i >> 4, g = i & 15;
            uint32_t sw = swz256(r, g);
            size_t go = ko + (size_t)r * HD + g * 8;
            cp_async16(st + sw, K16 + go);
            cp_async16(st + 16384 + sw, V16 + go);
        }
    };
    issue_kv(0, 0); CP_COMMIT();
    issue_kv(1, 1); CP_COMMIT();

    float of[16][4];
    #pragma unroll
    for (int i = 0; i < 16; i++)
        #pragma unroll
        for (int j = 0; j < 4; j++) of[i][j] = 0.f;
    float mrow0 = -1e30f, mrow1 = -1e30f, lrow0 = 0.f, lrow1 = 0.f;

    const int arow = wid * 16 + (lane & 15);
    const int agr  = lane >> 4;

    int slot = 0;
    int slot2 = 2;
    for (int jt = 0; jt < jend; jt++) {
        CP_WAIT1();
        __syncthreads();
        if (jt + 2 < jend) issue_kv(jt + 2, slot2);
        CP_COMMIT();

        const uint32_t st = sb + F_OFF_ST + slot * F_STAGE;
        const int t0 = jt * FBN;

        float sf[8][4];
        #pragma unroll
        for (int i = 0; i < 8; i++)
            #pragma unroll
            for (int j = 0; j < 4; j++) sf[i][j] = 0.f;

        #pragma unroll
        for (int kt = 0; kt < 8; kt++) {
            uint32_t a[4];
            ldsm4(a, sb + F_OFF_Q + swz256(arow, kt * 2 + agr));
            #pragma unroll
            for (int nb = 0; nb < 4; nb++) {
                uint32_t b[4];
                ldsm4(b, st + swz256(nb * 16 + (lane & 15), kt * 2 + agr));
                mma_f16(sf[nb * 2 + 0], a, b[0], b[2]);
                mma_f16(sf[nb * 2 + 1], a, b[1], b[3]);
            }
        }

        if (jt >= mask_start) {
            const int rb = m0 + wid * 16 + (lane >> 2);
            const int cb = t0 + (lane & 3) * 2;
            #pragma unroll
            for (int nt = 0; nt < 8; nt++) {
                const int c0 = cb + nt * 8;
                if (c0     > PREV_LEN + rb)     sf[nt][0] = -1e30f;
                if (c0 + 1 > PREV_LEN + rb)     sf[nt][1] = -1e30f;
                if (c0     > PREV_LEN + rb + 8) sf[nt][2] = -1e30f;
                if (c0 + 1 > PREV_LEN + rb + 8) sf[nt][3] = -1e30f;
            }
        }

        float mx0 = -1e30f, mx1 = -1e30f;
        #pragma unroll
        for (int nt = 0; nt < 8; nt++) {
            mx0 = fmaxf(mx0, fmaxf(sf[nt][0], sf[nt][1]));
            mx1 = fmaxf(mx1, fmaxf(sf[nt][2], sf[nt][3]));
        }
        mx0 = fmaxf(mx0, __shfl_xor_sync(0xFFFFFFFF, mx0, 1));
        mx0 = fmaxf(mx0, __shfl_xor_sync(0xFFFFFFFF, mx0, 2));
        mx1 = fmaxf(mx1, __shfl_xor_sync(0xFFFFFFFF, mx1, 1));
        mx1 = fmaxf(mx1, __shfl_xor_sync(0xFFFFFFFF, mx1, 2));
        const float nm0 = fmaxf(mrow0, mx0);
        const float nm1 = fmaxf(mrow1, mx1);
        const float al0 = __expf(mrow0 - nm0);
        const float al1 = __expf(mrow1 - nm1);
        mrow0 = nm0; mrow1 = nm1;

        float rs0 = 0.f, rs1 = 0.f;
        #pragma unroll
        for (int nt = 0; nt < 8; nt++) {
            sf[nt][0] = __expf(sf[nt][0] - nm0);
            sf[nt][1] = __expf(sf[nt][1] - nm0);
            sf[nt][2] = __expf(sf[nt][2] - nm1);
            sf[nt][3] = __expf(sf[nt][3] - nm1);
            rs0 += sf[nt][0] + sf[nt][1];
            rs1 += sf[nt][2] + sf[nt][3];
        }
        rs0 += __shfl_xor_sync(0xFFFFFFFF, rs0, 1);
        rs0 += __shfl_xor_sync(0xFFFFFFFF, rs0, 2);
        rs1 += __shfl_xor_sync(0xFFFFFFFF, rs1, 1);
        rs1 += __shfl_xor_sync(0xFFFFFFFF, rs1, 2);
        lrow0 = lrow0 * al0 + rs0;
        lrow1 = lrow1 * al1 + rs1;

        #pragma unroll
        for (int nt = 0; nt < 16; nt++) {
            of[nt][0] *= al0; of[nt][1] *= al0;
            of[nt][2] *= al1; of[nt][3] *= al1;
        }

        #pragma unroll
        for (int kt = 0; kt < 4; kt++) {
            uint32_t a[4];
            a[0] = pack_f16(sf[2 * kt][0],     sf[2 * kt][1]);
            a[1] = pack_f16(sf[2 * kt][2],     sf[2 * kt][3]);
            a[2] = pack_f16(sf[2 * kt + 1][0], sf[2 * kt + 1][1]);
            a[3] = pack_f16(sf[2 * kt + 1][2], sf[2 * kt + 1][3]);
            const int vrow = kt * 16 + ((lane >> 3) & 1) * 8 + (lane & 7);
            #pragma unroll
            for (int nb = 0; nb < 8; nb++) {
                uint32_t b[4];
                ldsm4t(b, st + 16384 + swz256(vrow, nb * 2 + ((lane >> 4) & 1)));
                mma_f16(of[nb * 2 + 0], a, b[0], b[1]);
                mma_f16(of[nb * 2 + 1], a, b[2], b[3]);
            }
        }
        slot  = (slot  == 2) ? 0 : slot + 1;
        slot2 = (slot2 == 2) ? 0 : slot2 + 1;
    }

    const float inv0 = 1.f / lrow0;
    const float inv1 = 1.f / lrow1;
    const int b = bh >> 4, h = bh & 15;
    const int r0 = m0 + wid * 16 + (lane >> 2);
    #pragma unroll
    for (int nt = 0; nt < 16; nt++) {
        const int gc = h * HD + nt * 8 + (lane & 3) * 2;
        *(__half2*)(O16 + (size_t)(b * S_LEN + r0) * DIM + gc) =
            __floats2half2_rn(of[nt][0] * inv0, of[nt][1] * inv0);
        *(__half2*)(O16 + (size_t)(b * S_LEN + r0 + 8) * DIM + gc) =
            __floats2half2_rn(of[nt][2] * inv1, of[nt][3] * inv1);
    }
}

// ---------------- launch ----------------
extern "C" void kernel_launch(void* const* d_in, const int* in_sizes, int n_in,
                              void* d_out, int out_size)
{
    const float* x          = (const float*)d_in[0];
    const float* k_cache    = (const float*)d_in[1];
    const float* v_cache    = (const float*)d_in[2];
    const float* attn_norm_w= (const float*)d_in[3];
    const float* ffn_norm_w = (const float*)d_in[4];
    const float* wq = (const float*)d_in[5];
    const float* bq = (const float*)d_in[6];
    const float* wk = (const float*)d_in[7];
    const float* bk = (const float*)d_in[8];
    const float* wv = (const float*)d_in[9];
    const float* bv = (const float*)d_in[10];
    const float* wo = (const float*)d_in[11];
    const float* bo = (const float*)d_in[12];
    const float* w_gate = (const float*)d_in[13];
    const float* b_gate = (const float*)d_in[14];
    const float* w_val  = (const float*)d_in[15];
    const float* b_val  = (const float*)d_in[16];
    const float* w_proj = (const float*)d_in[17];
    const float* b_proj = (const float*)d_in[18];
    const float* fcos   = (const float*)d_in[19];
    const float* fsin   = (const float*)d_in[20];

    float* out_x = (float*)d_out;
    float* out_k = out_x + OUT_X_ELEMS;
    float* out_v = out_k + OUT_KV_ELEMS;

    float *p_x1;
    __half *p_hA16, *p_h216, *p_o16, *p_gt16;
    __half *p_q16, *p_k16, *p_v16;
    __half *p_wqkv, *p_wo, *p_wg, *p_wv2, *p_wp;

    cudaGetSymbolAddress((void**)&p_x1, g_x1);
    cudaGetSymbolAddress((void**)&p_hA16, g_hA16);
    cudaGetSymbolAddress((void**)&p_h216, g_h216);
    cudaGetSymbolAddress((void**)&p_o16,  g_o16);
    cudaGetSymbolAddress((void**)&p_gt16, g_gt16);
    cudaGetSymbolAddress((void**)&p_q16,  g_q16);
    cudaGetSymbolAddress((void**)&p_k16,  g_k16);
    cudaGetSymbolAddress((void**)&p_v16,  g_v16);
    cudaGetSymbolAddress((void**)&p_wqkv, g_wqkv);
    cudaGetSymbolAddress((void**)&p_wo,   g_wo);
    cudaGetSymbolAddress((void**)&p_wg,   g_wg);
    cudaGetSymbolAddress((void**)&p_wv2,  g_wv2);
    cudaGetSymbolAddress((void**)&p_wp,   g_wp);

    cudaFuncSetAttribute(gemm_mma<1>, cudaFuncAttributeMaxDynamicSharedMemorySize, GM_SMEM);
    cudaFuncSetAttribute(gemm_qkv,   cudaFuncAttributeMaxDynamicSharedMemorySize, GM_SMEM);
    cudaFuncSetAttribute(gemm_ffn,   cudaFuncAttributeMaxDynamicSharedMemorySize, GM_SMEM);
    cudaFuncSetAttribute(flash_mma,  cudaFuncAttributeMaxDynamicSharedMemorySize, F_SMEM);

    // ---- prep: rmsnorm(attn) + all weight conversions in one grid ----
    prep_kernel<<<ROWS + 16384, 256>>>(
        x, attn_norm_w, p_hA16,
        wq, wk, wv, wo, w_gate, w_val, w_proj,
        p_wqkv, p_wo, p_wg, p_wv2, p_wp);

    // ---- attention block (qkv GEMM + fused cache copy) ----
    gemm_qkv<<<dim3(26, 32), 256, GM_SMEM>>>(
        p_hA16, p_wqkv, bq, bk, bv, fcos, fsin,
        k_cache, v_cache, out_k, out_v, p_q16, p_k16, p_v16);

    flash_mma<<<dim3(S_LEN / FBM, BATCH * HEADS), 256, F_SMEM>>>(
        p_q16, p_k16, p_v16, p_o16);

    gemm_mma<1><<<dim3(8, 32), 256, GM_SMEM>>>(
        p_o16, p_wo, bo, x, p_x1, nullptr, ROWS, DIM, DIM);

    // ---- ffn block ----
    rmsnorm_h<<<ROWS, 256>>>(p_x1, ffn_norm_w, p_h216);
    gemm_ffn<<<dim3(64, 32), 256, GM_SMEM>>>(
        p_h216, p_wg, p_wv2, b_gate, b_val, p_gt16);
    gemm_mma<1><<<dim3(8, 32), 256, GM_SMEM>>>(
        p_gt16, p_wp, b_proj, p_x1, out_x, nullptr, ROWS, DIM, FF_DIM);
}

// round 14
// speedup vs baseline: 1.1821x; 1.0509x over previous
#include <cuda_runtime.h>
#include <cuda_bf16.h>
#include <cuda_fp16.h>
#include <cstdint>

// ---------------- problem constants ----------------
#define BATCH 2
#define S_LEN 2048
#define PREV_LEN 1024
#define T_LEN 3072
#define DIM 2048
#define HEADS 16
#define HD 128
#define FF_DIM 8192
#define ROWS (BATCH * S_LEN)  // 4096
#define QK_SCALE 0.08838834764831845f

#define OUT_X_ELEMS  (BATCH * S_LEN * DIM)
#define OUT_KV_ELEMS (BATCH * HEADS * T_LEN * HD)

// ================= PTX helpers (portable sm_80+) ====
__device__ __forceinline__ uint32_t smem_u32(const void* p) {
    uint32_t a;
    asm("{ .reg .u64 t; cvta.to.shared.u64 t, %1; cvt.u32.u64 %0, t; }" : "=r"(a) : "l"(p));
    return a;
}
__device__ __forceinline__ void cp_async16(uint32_t smem, const void* g) {
    asm volatile("cp.async.cg.shared.global [%0], [%1], 16;" :: "r"(smem), "l"(g) : "memory");
}
#define CP_COMMIT() asm volatile("cp.async.commit_group;" ::: "memory")
#define CP_WAIT6()  asm volatile("cp.async.wait_group 6;" ::: "memory")
#define CP_WAIT4()  asm volatile("cp.async.wait_group 4;" ::: "memory")
#define CP_WAIT1()  asm volatile("cp.async.wait_group 1;" ::: "memory")

__device__ __forceinline__ void ldsm4(uint32_t* r, uint32_t addr) {
    asm volatile("ldmatrix.sync.aligned.m8n8.x4.shared.b16 {%0,%1,%2,%3}, [%4];"
        : "=r"(r[0]), "=r"(r[1]), "=r"(r[2]), "=r"(r[3]) : "r"(addr));
}
__device__ __forceinline__ void ldsm4t(uint32_t* r, uint32_t addr) {
    asm volatile("ldmatrix.sync.aligned.m8n8.x4.trans.shared.b16 {%0,%1,%2,%3}, [%4];"
        : "=r"(r[0]), "=r"(r[1]), "=r"(r[2]), "=r"(r[3]) : "r"(addr));
}
__device__ __forceinline__ void mma_f16(float* c, const uint32_t* a, uint32_t b0, uint32_t b1) {
    asm volatile(
        "mma.sync.aligned.m16n8k16.row.col.f32.f16.f16.f32 "
        "{%0,%1,%2,%3}, {%4,%5,%6,%7}, {%8,%9}, {%0,%1,%2,%3};"
        : "+f"(c[0]), "+f"(c[1]), "+f"(c[2]), "+f"(c[3])
        : "r"(a[0]), "r"(a[1]), "r"(a[2]), "r"(a[3]), "r"(b0), "r"(b1));
}
__device__ __forceinline__ uint32_t pack_f16(float a, float b) {
    __half2 t = __floats2half2_rn(a, b);
    return *(uint32_t*)&t;
}

// ---------------- scratch (device globals) --------
__device__ float g_x1 [ROWS * DIM];
__device__ __half g_hA16 [ROWS * DIM];
__device__ __half g_h216 [ROWS * DIM];
__device__ __half g_o16  [ROWS * DIM];
__device__ __half g_gt16 [ROWS * FF_DIM];
__device__ __half g_q16 [ROWS * DIM];
__device__ __half g_k16 [OUT_KV_ELEMS];
__device__ __half g_v16 [OUT_KV_ELEMS];
__device__ __half g_wqkv[3 * DIM * DIM];
__device__ __half g_wo  [DIM * DIM];
__device__ __half g_wg  [DIM * FF_DIM];
__device__ __half g_wv2 [DIM * FF_DIM];
__device__ __half g_wp  [FF_DIM * DIM];

// =====================================================================
// prep kernel (proven): rmsnorm rows + weight conversion tiles.
// =====================================================================
__global__ __launch_bounds__(256) void prep_kernel(
    const float* __restrict__ x, const float* __restrict__ anw,
    __half* __restrict__ hA,
    const float* __restrict__ wq, const float* __restrict__ wk,
    const float* __restrict__ wv, const float* __restrict__ wo,
    const float* __restrict__ wg, const float* __restrict__ wv2,
    const float* __restrict__ wp,
    __half* __restrict__ Tqkv, __half* __restrict__ Two,
    __half* __restrict__ Twg, __half* __restrict__ Twv2,
    __half* __restrict__ Twp)
{
    __shared__ float sm[32 * 133];
    const int tid = threadIdx.x;
    const int bid = blockIdx.x;

    if (bid < ROWS) {
        const float* xp = x + (size_t)bid * DIM + tid * 8;
        float4 a = *(const float4*)xp;
        float4 b = *(const float4*)(xp + 4);
        float s = a.x*a.x + a.y*a.y + a.z*a.z + a.w*a.w
                + b.x*b.x + b.y*b.y + b.z*b.z + b.w*b.w;
        sm[tid] = s;
        __syncthreads();
        #pragma unroll
        for (int off = 128; off > 0; off >>= 1) {
            if (tid < off) sm[tid] += sm[tid + off];
            __syncthreads();
        }
        float scale = rsqrtf(sm[0] * (1.0f / DIM) + 1e-6f);
        const float* wpt = anw + tid * 8;
        float4 wa = *(const float4*)wpt;
        float4 wb = *(const float4*)(wpt + 4);
        float y[8];
        y[0] = a.x*scale*wa.x; y[1] = a.y*scale*wa.y; y[2] = a.z*scale*wa.z; y[3] = a.w*scale*wa.w;
        y[4] = b.x*scale*wb.x; y[5] = b.y*scale*wb.y; y[6] = b.z*scale*wb.z; y[7] = b.w*scale*wb.w;
        __align__(16) __half hv[8];
        #pragma unroll
        for (int j = 0; j < 8; j++) hv[j] = __float2half(y[j]);
        *(uint4*)(hA + (size_t)bid * DIM + tid * 8) = *(const uint4*)hv;
        return;
    }

    const int cid = bid - ROWS;
    const float* W; __half* T; int N, K, kb, nb;
    if (cid < 3072) {
        const int mat = cid / 1024, b = cid % 1024;
        W = (mat == 0) ? wq : ((mat == 1) ? wk : wv);
        T = Tqkv + (size_t)mat * DIM * DIM;
        N = DIM; K = DIM; kb = b % 64; nb = b / 64;
    } else if (cid < 4096) {
        const int b = cid - 3072;
        W = wo; T = Two; N = DIM; K = DIM; kb = b % 64; nb = b / 64;
    } else if (cid < 8192) {
        const int b = cid - 4096;
        W = wg; T = Twg; N = FF_DIM; K = DIM; kb = b % 64; nb = b / 64;
    } else if (cid < 12288) {
        const int b = cid - 8192;
        W = wv2; T = Twv2; N = FF_DIM; K = DIM; kb = b % 64; nb = b / 64;
    } else {
        const int b = cid - 12288;
        W = wp; T = Twp; N = DIM; K = FF_DIM; kb = b % 256; nb = b / 256;
    }
    const int k0 = kb * 32, n0 = nb * 128;
    {
        const int kr = tid >> 3;
        const int nq = (tid & 7) * 16;
        const float* src = W + (size_t)(k0 + kr) * N + n0 + nq;
        #pragma unroll
        for (int u = 0; u < 4; u++) {
            float4 v = *(const float4*)(src + u * 4);
            sm[kr * 133 + nq + u * 4 + 0] = v.x;
            sm[kr * 133 + nq + u * 4 + 1] = v.y;
            sm[kr * 133 + nq + u * 4 + 2] = v.z;
            sm[kr * 133 + nq + u * 4 + 3] = v.w;
        }
    }
    __syncthreads();
    const int n = tid >> 1;
    const int q = tid & 1;
    __align__(16) __half hv[16];
    #pragma unroll
    for (int u = 0; u < 16; u++)
        hv[u] = __float2half(sm[(q * 16 + u) * 133 + n]);
    const size_t off = (size_t)(n0 + n) * K + k0 + q * 16;
    *(uint4*)(T + off)     = *(const uint4*)(hv);
    *(uint4*)(T + off + 8) = *(const uint4*)(hv + 8);
}

// =====================================================================
// rmsnorm -> single fp16 row-major (ffn block)
// =====================================================================
__global__ __launch_bounds__(256) void rmsnorm_h(
    const float* __restrict__ x, const float* __restrict__ w,
    __half* __restrict__ O16)
{
    __shared__ float red[256];
    const int tid = threadIdx.x;
    const int m = blockIdx.x;
    const float* xp = x + (size_t)m * DIM + tid * 8;
    float4 a = *(const float4*)xp;
    float4 b = *(const float4*)(xp + 4);
    float s = a.x*a.x + a.y*a.y + a.z*a.z + a.w*a.w
            + b.x*b.x + b.y*b.y + b.z*b.z + b.w*b.w;
    red[tid] = s;
    __syncthreads();
    #pragma unroll
    for (int off = 128; off > 0; off >>= 1) {
        if (tid < off) red[tid] += red[tid + off];
        __syncthreads();
    }
    float scale = rsqrtf(red[0] * (1.0f / DIM) + 1e-6f);
    const float* wp = w + tid * 8;
    float4 wa = *(const float4*)wp;
    float4 wb = *(const float4*)(wp + 4);
    float y[8];
    y[0] = a.x*scale*wa.x; y[1] = a.y*scale*wa.y; y[2] = a.z*scale*wa.z; y[3] = a.w*scale*wa.w;
    y[4] = b.x*scale*wb.x; y[5] = b.y*scale*wb.y; y[6] = b.z*scale*wb.z; y[7] = b.w*scale*wb.w;
    __align__(16) __half hv[8];
    #pragma unroll
    for (int j = 0; j < 8; j++) hv[j] = __float2half(y[j]);
    *(uint4*)(O16 + (size_t)m * DIM + tid * 8) = *(const uint4*)hv;
}

// =====================================================================
// Shared swizzle for 64B rows (K-chunk 32 fp16)
// =====================================================================
__device__ __forceinline__ uint32_t swz(int r, int g) {
    return (uint32_t)(r * 64 + ((g ^ ((r >> 1) & 3)) << 4));
}

// =====================================================================
// 2-CTA/SM GEMM core: CTA 128(M)x128(N), warp 64x32 (2m x 4n), 8 warps,
// K-chunk 32, 6-stage x 16KB cp.async ring (96KB/CTA -> 2 CTAs/SM).
// =====================================================================
#define G2_STAGES 6
#define G2_STAGE_BYTES 16384
#define G2_SMEM (G2_STAGES * G2_STAGE_BYTES)   // 98304
#define G2_OFF_A 0
#define G2_OFF_B 8192

#define G2_ISSUE_LAMBDA(A16, B16, m0, n0, K)                                    \
    auto issue_stage = [&](int kc, int slot) {                                  \
        const uint32_t st = sb + slot * G2_STAGE_BYTES;                         \
        const int kelem = kc * 32 + lg * 8;                                     \
        _Pragma("unroll")                                                       \
        for (int i = 0; i < 2; i++) {                                           \
            const int r = lr + i * 64;                                          \
            const uint32_t sw = swz(r, lg);                                     \
            cp_async16(st + G2_OFF_A + sw, A16 + (size_t)(m0 + r) * K + kelem); \
            cp_async16(st + G2_OFF_B + sw, B16 + (size_t)(n0 + r) * K + kelem); \
        }                                                                       \
    };

// mainloop body computing acc[4][4][4]; shared by gemm_mma2/gemm_qkv2
template<typename IssueF>
__device__ __forceinline__ void g2_mainloop(
    float (&acc)[4][4][4], uint32_t sb, int nk, int wm, int wn, int lane,
    IssueF issue_stage)
{
    #pragma unroll
    for (int p = 0; p < 5; p++) { issue_stage(p, p); CP_COMMIT(); }

    int slot = 0, slotN = 5;
    for (int kc = 0; kc < nk; kc++) {
        CP_WAIT4();
        __syncthreads();
        if (kc + 5 < nk) issue_stage(kc + 5, slotN);
        CP_COMMIT();

        const uint32_t st = sb + slot * G2_STAGE_BYTES;
        #pragma unroll
        for (int h = 0; h < 2; h++) {
            uint32_t a[4][4];
            #pragma unroll
            for (int mi = 0; mi < 4; mi++) {
                const int r = wm * 64 + mi * 16 + (lane & 15);
                ldsm4(a[mi], st + G2_OFF_A + swz(r, h * 2 + (lane >> 4)));
            }
            #pragma unroll
            for (int ng = 0; ng < 2; ng++) {
                uint32_t b[4];
                const int r = wn * 32 + ng * 16 + (lane & 15);
                ldsm4(b, st + G2_OFF_B + swz(r, h * 2 + (lane >> 4)));
                #pragma unroll
                for (int mi = 0; mi < 4; mi++) {
                    mma_f16(acc[mi][ng * 2 + 0], a[mi], b[0], b[2]);
                    mma_f16(acc[mi][ng * 2 + 1], a[mi], b[1], b[3]);
                }
            }
        }
        slot  = (slot  == G2_STAGES - 1) ? 0 : slot + 1;
        slotN = (slotN == G2_STAGES - 1) ? 0 : slotN + 1;
    }
}

// =====================================================================
// Generic GEMM v2 (MODE 1): C = A@B + bias + extra (fp32 out)
// =====================================================================
template<int MODE>
__global__ void __launch_bounds__(256, 2) gemm_mma2(
    const __half* __restrict__ A16, const __half* __restrict__ B16,
    const float* __restrict__ bias, const float* __restrict__ extra,
    float* __restrict__ C, int M, int N, int K)
{
    extern __shared__ char smraw[];
    const uint32_t sb = smem_u32(smraw);
    const int tid = threadIdx.x;
    const int wid = tid >> 5;
    const int lane = tid & 31;
    const int wm = wid & 1;
    const int wn = wid >> 1;
    const int m0 = blockIdx.y * 128;
    const int n0 = blockIdx.x * 128;
    const int nk = K >> 5;
    const int lr = tid >> 2;
    const int lg = tid & 3;

    float acc[4][4][4];
    #pragma unroll
    for (int a = 0; a < 4; a++)
        #pragma unroll
        for (int b = 0; b < 4; b++)
            #pragma unroll
            for (int c = 0; c < 4; c++) acc[a][b][c] = 0.f;

    G2_ISSUE_LAMBDA(A16, B16, m0, n0, K)
    g2_mainloop(acc, sb, nk, wm, wn, lane, issue_stage);

    const int mb = m0 + wm * 64;
    const int nb = n0 + wn * 32;
    #pragma unroll
    for (int mi = 0; mi < 4; mi++) {
        #pragma unroll
        for (int j = 0; j < 4; j++) {
            const int row = mb + mi * 16 + (lane >> 2);
            const int col = nb + j * 8 + (lane & 3) * 2;
            const float b0 = bias[col], b1 = bias[col + 1];
            #pragma unroll
            for (int half = 0; half < 2; half++) {
                const int rr = row + half * 8;
                float v0 = acc[mi][j][half * 2 + 0] + b0;
                float v1 = acc[mi][j][half * 2 + 1] + b1;
                if (MODE == 1) {
                    const float* ep = extra + (size_t)rr * N + col;
                    v0 += ep[0]; v1 += ep[1];
                }
                *(float2*)(C + (size_t)rr * N + col) = make_float2(v0, v1);
            }
        }
    }
}

// =====================================================================
// Fused QKV GEMM v2 + cache copy. B = concat[wq|wk|wv] (N=6144).
// grid (50, 32): bx < 48 -> 128x128 GEMM tile; bx >= 48 -> copy CTA.
// =====================================================================
__global__ void __launch_bounds__(256, 2) gemm_qkv2(
    const __half* __restrict__ A16, const __half* __restrict__ B16,
    const float* __restrict__ bq, const float* __restrict__ bk, const float* __restrict__ bv,
    const float* __restrict__ cosb, const float* __restrict__ sinb,
    const float* __restrict__ k_cache, const float* __restrict__ v_cache,
    float* __restrict__ out_k, float* __restrict__ out_v,
    __half* __restrict__ Q16, __half* __restrict__ K16, __half* __restrict__ V16)
{
    extern __shared__ char smraw[];
    const int tid = threadIdx.x;

    if (blockIdx.x >= 48) {
        // ---- cache copy path (64 CTAs grid-stride over 2^21 float4) ----
        const int cidx = (blockIdx.x - 48) * 32 + blockIdx.y;
        for (int idx = cidx * 256 + tid; idx < (1 << 21); idx += 64 * 256) {
            const int z = idx >> 20;
            const int i = idx & ((1 << 20) - 1);
            const float* in = z ? v_cache : k_cache;
            float* out = z ? out_v : out_k;
            __half* H16 = z ? V16 : K16;
            const int bh  = i >> 15;
            const int rem = i & 32767;
            float4 v = ((const float4*)in)[i];
            size_t off4 = (size_t)bh * (T_LEN * HD / 4) + rem;
            ((float4*)out)[off4] = v;
            __align__(8) __half hv[4];
            hv[0] = __float2half(v.x); hv[1] = __float2half(v.y);
            hv[2] = __float2half(v.z); hv[3] = __float2half(v.w);
            *(uint2*)(H16 + off4 * 4) = *(const uint2*)hv;
        }
        return;
    }

    const uint32_t sb = smem_u32(smraw);
    const int wid = tid >> 5;
    const int lane = tid & 31;
    const int wm = wid & 1;
    const int wn = wid >> 1;
    const int m0 = blockIdx.y * 128;
    const int n0 = blockIdx.x * 128;
    const int K = DIM;
    const int nk = K >> 5;
    const int lr = tid >> 2;
    const int lg = tid & 3;
    const int sec = n0 >> 11;
    const float* bias = (sec == 0) ? bq : ((sec == 1) ? bk : bv);

    float acc[4][4][4];
    #pragma unroll
    for (int a = 0; a < 4; a++)
        #pragma unroll
        for (int b = 0; b < 4; b++)
            #pragma unroll
            for (int c = 0; c < 4; c++) acc[a][b][c] = 0.f;

    G2_ISSUE_LAMBDA(A16, B16, m0, n0, K)
    g2_mainloop(acc, sb, nk, wm, wn, lane, issue_stage);

    const int mb = m0 + wm * 64;
    const int nb = n0 + wn * 32;
    #pragma unroll
    for (int mi = 0; mi < 4; mi++) {
        #pragma unroll
        for (int j = 0; j < 4; j++) {
            const int row = mb + mi * 16 + (lane >> 2);
            const int col = nb + j * 8 + (lane & 3) * 2;
            const float b0 = bias[col & 2047], b1 = bias[(col & 2047) + 1];
            const int nc = col & 2047;
            const int h = nc >> 7;
            const int d = nc & 127;
            #pragma unroll
            for (int half = 0; half < 2; half++) {
                const int rr = row + half * 8;
                float v0 = acc[mi][j][half * 2 + 0] + b0;
                float v1 = acc[mi][j][half * 2 + 1] + b1;
                const int bi = rr >> 11;
                const int s = rr & 2047;
                if (sec < 2) {
                    const int i2 = d >> 1;
                    const float c = cosb[(PREV_LEN + s) * 64 + i2];
                    const float sn = sinb[(PREV_LEN + s) * 64 + i2];
                    const float r0 = v0 * c - v1 * sn;
                    const float r1 = v0 * sn + v1 * c;
                    if (sec == 0) {
                        *(__half2*)(Q16 + ((size_t)(bi * HEADS + h) * S_LEN + s) * HD + d) =
                            __floats2half2_rn(r0 * QK_SCALE, r1 * QK_SCALE);
                    } else {
                        const size_t off = ((size_t)(bi * HEADS + h) * T_LEN + PREV_LEN + s) * HD + d;
                        *(float2*)(out_k + off) = make_float2(r0, r1);
                        *(__half2*)(K16 + off) = __floats2half2_rn(r0, r1);
                    }
                } else {
                    const size_t off = ((size_t)(bi * HEADS + h) * T_LEN + PREV_LEN + s) * HD + d;
                    *(float2*)(out_v + off) = make_float2(v0, v1);
                    *(__half2*)(V16 + off) = __floats2half2_rn(v0, v1);
                }
            }
        }
    }
}

// =====================================================================
// Fused FFN gate+val GEMM (R10 proven, unchanged): CTA 128x128,
// K-chunk 32, 8 stages x 24KB.
// =====================================================================
#define GM_STAGE_BYTES 24576
#define GM_SMEM (8 * GM_STAGE_BYTES)   // 196608
#define FO_A  0
#define FO_BG 8192
#define FO_BV 16384

__global__ void __launch_bounds__(256, 1) gemm_ffn(
    const __half* __restrict__ A16,
    const __half* __restrict__ Bg, const __half* __restrict__ Bv,
    const float* __restrict__ bias_g, const float* __restrict__ bias_v,
    __half* __restrict__ C16)
{
    extern __shared__ char smraw[];
    const uint32_t sb = smem_u32(smraw);
    const int tid = threadIdx.x;
    const int wid = tid >> 5;
    const int lane = tid & 31;
    const int wm = wid & 1;
    const int wn = wid >> 1;
    const int m0 = blockIdx.y * 128;
    const int n0 = blockIdx.x * 128;
    const int K = DIM;
    const int nk = K >> 5;
    const int lr = tid >> 2;
    const int lg = tid & 3;

    float ag[4][4][4], av[4][4][4];
    #pragma unroll
    for (int a = 0; a < 4; a++)
        #pragma unroll
        for (int b = 0; b < 4; b++)
            #pragma unroll
            for (int c = 0; c < 4; c++) { ag[a][b][c] = 0.f; av[a][b][c] = 0.f; }

    auto issue_stage = [&](int kc, int slot) {
        const uint32_t st = sb + slot * GM_STAGE_BYTES;
        const int kelem = kc * 32 + lg * 8;
        #pragma unroll
        for (int i = 0; i < 2; i++) {
            const int r = lr + i * 64;
            const uint32_t sw = swz(r, lg);
            cp_async16(st + FO_A  + sw, A16 + (size_t)(m0 + r) * K + kelem);
            cp_async16(st + FO_BG + sw, Bg  + (size_t)(n0 + r) * K + kelem);
            cp_async16(st + FO_BV + sw, Bv  + (size_t)(n0 + r) * K + kelem);
        }
    };

    #pragma unroll
    for (int p = 0; p < 7; p++) { issue_stage(p, p); CP_COMMIT(); }

    for (int kc = 0; kc < nk; kc++) {
        CP_WAIT6();
        __syncthreads();
        if (kc + 7 < nk) issue_stage(kc + 7, (kc + 7) & 7);
        CP_COMMIT();

        const uint32_t st = sb + (kc & 7) * GM_STAGE_BYTES;
        #pragma unroll
        for (int h = 0; h < 2; h++) {
            uint32_t a[4][4];
            #pragma unroll
            for (int mi = 0; mi < 4; mi++) {
                const int r = wm * 64 + mi * 16 + (lane & 15);
                ldsm4(a[mi], st + FO_A + swz(r, h * 2 + (lane >> 4)));
            }
            #pragma unroll
            for (int ng = 0; ng < 2; ng++) {
                const int r = wn * 32 + ng * 16 + (lane & 15);
                const uint32_t sw = swz(r, h * 2 + (lane >> 4));
                uint32_t bg[4], bv[4];
                ldsm4(bg, st + FO_BG + sw);
                ldsm4(bv, st + FO_BV + sw);
                #pragma unroll
                for (int mi = 0; mi < 4; mi++) {
                    mma_f16(ag[mi][ng * 2 + 0], a[mi], bg[0], bg[2]);
                    mma_f16(ag[mi][ng * 2 + 1], a[mi], bg[1], bg[3]);
                    mma_f16(av[mi][ng * 2 + 0], a[mi], bv[0], bv[2]);
                    mma_f16(av[mi][ng * 2 + 1], a[mi], bv[1], bv[3]);
                }
            }
        }
    }

    const int mb = m0 + wm * 64;
    const int nb = n0 + wn * 32;
    #pragma unroll
    for (int mi = 0; mi < 4; mi++) {
        #pragma unroll
        for (int j = 0; j < 4; j++) {
            const int row = mb + mi * 16 + (lane >> 2);
            const int col = nb + j * 8 + (lane & 3) * 2;
            const float bg0 = bias_g[col], bg1 = bias_g[col + 1];
            const float bv0 = bias_v[col], bv1 = bias_v[col + 1];
            #pragma unroll
            for (int half = 0; half < 2; half++) {
                const int rr = row + half * 8;
                float gv0 = ag[mi][j][half * 2 + 0] + bg0;
                float gv1 = ag[mi][j][half * 2 + 1] + bg1;
                float vv0 = av[mi][j][half * 2 + 0] + bv0;
                float vv1 = av[mi][j][half * 2 + 1] + bv1;
                float o0 = gv0 / (1.f + __expf(-gv0)) * vv0;
                float o1 = gv1 / (1.f + __expf(-gv1)) * vv1;
                *(__half2*)(C16 + (size_t)rr * FF_DIM + col) = __floats2half2_rn(o0, o1);
            }
        }
    }
}

// =====================================================================
// HMMA flash attention (proven): fp16 1-pass QK, 3-stage KV,
// single barrier per tile.
// =====================================================================
#define FBM 128
#define FBN 64
#define F_OFF_Q  0
#define F_OFF_ST 32768
#define F_STAGE  32768
#define F_SMEM   (F_OFF_ST + 3 * F_STAGE)   // 131072

__device__ __forceinline__ uint32_t swz256(int r, int g) {
    return (uint32_t)((r << 8) + (((g ^ (r & 7)) & 15) << 4));
}

__global__ void __launch_bounds__(256) flash_mma(
    const __half* __restrict__ Q16, const __half* __restrict__ K16,
    const __half* __restrict__ V16, __half* __restrict__ O16)
{
    extern __shared__ char smraw[];
    const uint32_t sb = smem_u32(smraw);
    const int tid = threadIdx.x;
    const int wid = tid >> 5;
    const int lane = tid & 31;
    const int mtile = gridDim.x - 1 - blockIdx.x;
    const int bh = blockIdx.y;
    const int m0 = mtile * FBM;
    const int jend = (PREV_LEN + m0 + FBM) / FBN;
    const int mask_start = (PREV_LEN + m0) / FBN;

    {
        const size_t qo = ((size_t)bh * S_LEN + m0) * HD;
        for (int i = tid; i < 2048; i += 256) {
            int r = i >> 4, g = i & 15;
            cp_async16(sb + F_OFF_Q + swz256(r, g), Q16 + qo + (size_t)r * HD + g * 8);
        }
        CP_COMMIT();
    }

    auto issue_kv = [&](int jt, int slot) {
        const uint32_t st = sb + F_OFF_ST + slot * F_STAGE;
        const size_t ko = ((size_t)bh * T_LEN + jt * FBN) * HD;
        for (int i = tid; i < 1024; i += 256) {
            int r = i >> 4, g = i & 15;
            uint32_t sw = swz256(r, g);
            size_t go = ko + (size_t)r * HD + g * 8;
            cp_async16(st + sw, K16 + go);
            cp_async16(st + 16384 + sw, V16 + go);
        }
    };
    issue_kv(0, 0); CP_COMMIT();
    issue_kv(1, 1); CP_COMMIT();

    float of[16][4];
    #pragma unroll
    for (int i = 0; i < 16; i++)
        #pragma unroll
        for (int j = 0; j < 4; j++) of[i][j] = 0.f;
    float mrow0 = -1e30f, mrow1 = -1e30f, lrow0 = 0.f, lrow1 = 0.f;

    const int arow = wid * 16 + (lane & 15);
    const int agr  = lane >> 4;

    int slot = 0;
    int slot2 = 2;
    for (int jt = 0; jt < jend; jt++) {
        CP_WAIT1();
        __syncthreads();
        if (jt + 2 < jend) issue_kv(jt + 2, slot2);
        CP_COMMIT();

        const uint32_t st = sb + F_OFF_ST + slot * F_STAGE;
        const int t0 = jt * FBN;

        float sf[8][4];
        #pragma unroll
        for (int i = 0; i < 8; i++)
            #pragma unroll
            for (int j = 0; j < 4; j++) sf[i][j] = 0.f;

        #pragma unroll
        for (int kt = 0; kt < 8; kt++) {
            uint32_t a[4];
            ldsm4(a, sb + F_OFF_Q + swz256(arow, kt * 2 + agr));
            #pragma unroll
            for (int nb = 0; nb < 4; nb++) {
                uint32_t b[4];
                ldsm4(b, st + swz256(nb * 16 + (lane & 15), kt * 2 + agr));
                mma_f16(sf[nb * 2 + 0], a, b[0], b[2]);
                mma_f16(sf[nb * 2 + 1], a, b[1], b[3]);
            }
        }

        if (jt >= mask_start) {
            const int rb = m0 + wid * 16 + (lane >> 2);
            const int cb = t0 + (lane & 3) * 2;
            #pragma unroll
            for (int nt = 0; nt < 8; nt++) {
                const int c0 = cb + nt * 8;
                if (c0     > PREV_LEN + rb)     sf[nt][0] = -1e30f;
                if (c0 + 1 > PREV_LEN + rb)     sf[nt][1] = -1e30f;
                if (c0     > PREV_LEN + rb + 8) sf[nt][2] = -1e30f;
                if (c0 + 1 > PREV_LEN + rb + 8) sf[nt][3] = -1e30f;
            }
        }

        float mx0 = -1e30f, mx1 = -1e30f;
        #pragma unroll
        for (int nt = 0; nt < 8; nt++) {
            mx0 = fmaxf(mx0, fmaxf(sf[nt][0], sf[nt][1]));
            mx1 = fmaxf(mx1, fmaxf(sf[nt][2], sf[nt][3]));
        }
        mx0 = fmaxf(mx0, __shfl_xor_sync(0xFFFFFFFF, mx0, 1));
        mx0 = fmaxf(mx0, __shfl_xor_sync(0xFFFFFFFF, mx0, 2));
        mx1 = fmaxf(mx1, __shfl_xor_sync(0xFFFFFFFF, mx1, 1));
        mx1 = fmaxf(mx1, __shfl_xor_sync(0xFFFFFFFF, mx1, 2));
        const float nm0 = fmaxf(mrow0, mx0);
        const float nm1 = fmaxf(mrow1, mx1);
        const float al0 = __expf(mrow0 - nm0);
        const float al1 = __expf(mrow1 - nm1);
        mrow0 = nm0; mrow1 = nm1;

        float rs0 = 0.f, rs1 = 0.f;
        #pragma unroll
        for (int nt = 0; nt < 8; nt++) {
            sf[nt][0] = __expf(sf[nt][0] - nm0);
            sf[nt][1] = __expf(sf[nt][1] - nm0);
            sf[nt][2] = __expf(sf[nt][2] - nm1);
            sf[nt][3] = __expf(sf[nt][3] - nm1);
            rs0 += sf[nt][0] + sf[nt][1];
            rs1 += sf[nt][2] + sf[nt][3];
        }
        rs0 += __shfl_xor_sync(0xFFFFFFFF, rs0, 1);
        rs0 += __shfl_xor_sync(0xFFFFFFFF, rs0, 2);
        rs1 += __shfl_xor_sync(0xFFFFFFFF, rs1, 1);
        rs1 += __shfl_xor_sync(0xFFFFFFFF, rs1, 2);
        lrow0 = lrow0 * al0 + rs0;
        lrow1 = lrow1 * al1 + rs1;

        #pragma unroll
        for (int nt = 0; nt < 16; nt++) {
            of[nt][0] *= al0; of[nt][1] *= al0;
            of[nt][2] *= al1; of[nt][3] *= al1;
        }

        #pragma unroll
        for (int kt = 0; kt < 4; kt++) {
            uint32_t a[4];
            a[0] = pack_f16(sf[2 * kt][0],     sf[2 * kt][1]);
            a[1] = pack_f16(sf[2 * kt][2],     sf[2 * kt][3]);
            a[2] = pack_f16(sf[2 * kt + 1][0], sf[2 * kt + 1][1]);
            a[3] = pack_f16(sf[2 * kt + 1][2], sf[2 * kt + 1][3]);
            const int vrow = kt * 16 + ((lane >> 3) & 1) * 8 + (lane & 7);
            #pragma unroll
            for (int nb = 0; nb < 8; nb++) {
                uint32_t b[4];
                ldsm4t(b, st + 16384 + swz256(vrow, nb * 2 + ((lane >> 4) & 1)));
                mma_f16(of[nb * 2 + 0], a, b[0], b[1]);
                mma_f16(of[nb * 2 + 1], a, b[2], b[3]);
            }
        }
        slot  = (slot  == 2) ? 0 : slot + 1;
        slot2 = (slot2 == 2) ? 0 : slot2 + 1;
    }

    const float inv0 = 1.f / lrow0;
    const float inv1 = 1.f / lrow1;
    const int b = bh >> 4, h = bh & 15;
    const int r0 = m0 + wid * 16 + (lane >> 2);
    #pragma unroll
    for (int nt = 0; nt < 16; nt++) {
        const int gc = h * HD + nt * 8 + (lane & 3) * 2;
        *(__half2*)(O16 + (size_t)(b * S_LEN + r0) * DIM + gc) =
            __floats2half2_rn(of[nt][0] * inv0, of[nt][1] * inv0);
        *(__half2*)(O16 + (size_t)(b * S_LEN + r0 + 8) * DIM + gc) =
            __floats2half2_rn(of[nt][2] * inv1, of[nt][3] * inv1);
    }
}

// ---------------- launch ----------------
extern "C" void kernel_launch(void* const* d_in, const int* in_sizes, int n_in,
                              void* d_out, int out_size)
{
    const float* x          = (const float*)d_in[0];
    const float* k_cache    = (const float*)d_in[1];
    const float* v_cache    = (const float*)d_in[2];
    const float* attn_norm_w= (const float*)d_in[3];
    const float* ffn_norm_w = (const float*)d_in[4];
    const float* wq = (const float*)d_in[5];
    const float* bq = (const float*)d_in[6];
    const float* wk = (const float*)d_in[7];
    const float* bk = (const float*)d_in[8];
    const float* wv = (const float*)d_in[9];
    const float* bv = (const float*)d_in[10];
    const float* wo = (const float*)d_in[11];
    const float* bo = (const float*)d_in[12];
    const float* w_gate = (const float*)d_in[13];
    const float* b_gate = (const float*)d_in[14];
    const float* w_val  = (const float*)d_in[15];
    const float* b_val  = (const float*)d_in[16];
    const float* w_proj = (const float*)d_in[17];
    const float* b_proj = (const float*)d_in[18];
    const float* fcos   = (const float*)d_in[19];
    const float* fsin   = (const float*)d_in[20];

    float* out_x = (float*)d_out;
    float* out_k = out_x + OUT_X_ELEMS;
    float* out_v = out_k + OUT_KV_ELEMS;

    float *p_x1;
    __half *p_hA16, *p_h216, *p_o16, *p_gt16;
    __half *p_q16, *p_k16, *p_v16;
    __half *p_wqkv, *p_wo, *p_wg, *p_wv2, *p_wp;

    cudaGetSymbolAddress((void**)&p_x1, g_x1);
    cudaGetSymbolAddress((void**)&p_hA16, g_hA16);
    cudaGetSymbolAddress((void**)&p_h216, g_h216);
    cudaGetSymbolAddress((void**)&p_o16,  g_o16);
    cudaGetSymbolAddress((void**)&p_gt16, g_gt16);
    cudaGetSymbolAddress((void**)&p_q16,  g_q16);
    cudaGetSymbolAddress((void**)&p_k16,  g_k16);
    cudaGetSymbolAddress((void**)&p_v16,  g_v16);
    cudaGetSymbolAddress((void**)&p_wqkv, g_wqkv);
    cudaGetSymbolAddress((void**)&p_wo,   g_wo);
    cudaGetSymbolAddress((void**)&p_wg,   g_wg);
    cudaGetSymbolAddress((void**)&p_wv2,  g_wv2);
    cudaGetSymbolAddress((void**)&p_wp,   g_wp);

    cudaFuncSetAttribute(gemm_mma2<1>, cudaFuncAttributeMaxDynamicSharedMemorySize, G2_SMEM);
    cudaFuncSetAttribute(gemm_qkv2,  cudaFuncAttributeMaxDynamicSharedMemorySize, G2_SMEM);
    cudaFuncSetAttribute(gemm_ffn,   cudaFuncAttributeMaxDynamicSharedMemorySize, GM_SMEM);
    cudaFuncSetAttribute(flash_mma,  cudaFuncAttributeMaxDynamicSharedMemorySize, F_SMEM);

    // ---- prep: rmsnorm(attn) + all weight conversions in one grid ----
    prep_kernel<<<ROWS + 16384, 256>>>(
        x, attn_norm_w, p_hA16,
        wq, wk, wv, wo, w_gate, w_val, w_proj,
        p_wqkv, p_wo, p_wg, p_wv2, p_wp);

    // ---- attention block (qkv GEMM + fused cache copy) ----
    gemm_qkv2<<<dim3(50, 32), 256, G2_SMEM>>>(
        p_hA16, p_wqkv, bq, bk, bv, fcos, fsin,
        k_cache, v_cache, out_k, out_v, p_q16, p_k16, p_v16);

    flash_mma<<<dim3(S_LEN / FBM, BATCH * HEADS), 256, F_SMEM>>>(
        p_q16, p_k16, p_v16, p_o16);

    gemm_mma2<1><<<dim3(16, 32), 256, G2_SMEM>>>(
        p_o16, p_wo, bo, x, p_x1, ROWS, DIM, DIM);

    // ---- ffn block ----
    rmsnorm_h<<<ROWS, 256>>>(p_x1, ffn_norm_w, p_h216);
    gemm_ffn<<<dim3(64, 32), 256, GM_SMEM>>>(
        p_h216, p_wg, p_wv2, b_gate, b_val, p_gt16);
    gemm_mma2<1><<<dim3(16, 32), 256, G2_SMEM>>>(
        p_gt16, p_wp, b_proj, p_x1, out_x, ROWS, DIM, FF_DIM);
}

// round 15
// speedup vs baseline: 1.2700x; 1.0743x over previous
#include <cuda_runtime.h>
#include <cuda_bf16.h>
#include <cuda_fp16.h>
#include <cstdint>

// ---------------- problem constants ----------------
#define BATCH 2
#define S_LEN 2048
#define PREV_LEN 1024
#define T_LEN 3072
#define DIM 2048
#define HEADS 16
#define HD 128
#define FF_DIM 8192
#define ROWS (BATCH * S_LEN)  // 4096
#define QK_SCALE 0.08838834764831845f

#define OUT_X_ELEMS  (BATCH * S_LEN * DIM)
#define OUT_KV_ELEMS (BATCH * HEADS * T_LEN * HD)

// ================= PTX helpers (portable sm_80+) ====
__device__ __forceinline__ uint32_t smem_u32(const void* p) {
    uint32_t a;
    asm("{ .reg .u64 t; cvta.to.shared.u64 t, %1; cvt.u32.u64 %0, t; }" : "=r"(a) : "l"(p));
    return a;
}
__device__ __forceinline__ void cp_async16(uint32_t smem, const void* g) {
    asm volatile("cp.async.cg.shared.global [%0], [%1], 16;" :: "r"(smem), "l"(g) : "memory");
}
#define CP_COMMIT() asm volatile("cp.async.commit_group;" ::: "memory")
#define CP_WAIT4()  asm volatile("cp.async.wait_group 4;" ::: "memory")
#define CP_WAIT1()  asm volatile("cp.async.wait_group 1;" ::: "memory")

__device__ __forceinline__ void ldsm4(uint32_t* r, uint32_t addr) {
    asm volatile("ldmatrix.sync.aligned.m8n8.x4.shared.b16 {%0,%1,%2,%3}, [%4];"
        : "=r"(r[0]), "=r"(r[1]), "=r"(r[2]), "=r"(r[3]) : "r"(addr));
}
__device__ __forceinline__ void ldsm4t(uint32_t* r, uint32_t addr) {
    asm volatile("ldmatrix.sync.aligned.m8n8.x4.trans.shared.b16 {%0,%1,%2,%3}, [%4];"
        : "=r"(r[0]), "=r"(r[1]), "=r"(r[2]), "=r"(r[3]) : "r"(addr));
}
__device__ __forceinline__ void mma_f16(float* c, const uint32_t* a, uint32_t b0, uint32_t b1) {
    asm volatile(
        "mma.sync.aligned.m16n8k16.row.col.f32.f16.f16.f32 "
        "{%0,%1,%2,%3}, {%4,%5,%6,%7}, {%8,%9}, {%0,%1,%2,%3};"
        : "+f"(c[0]), "+f"(c[1]), "+f"(c[2]), "+f"(c[3])
        : "r"(a[0]), "r"(a[1]), "r"(a[2]), "r"(a[3]), "r"(b0), "r"(b1));
}
__device__ __forceinline__ uint32_t pack_f16(float a, float b) {
    __half2 t = __floats2half2_rn(a, b);
    return *(uint32_t*)&t;
}

// ---------------- scratch (device globals) --------
__device__ float g_x1 [ROWS * DIM];
__device__ __half g_hA16 [ROWS * DIM];
__device__ __half g_h216 [ROWS * DIM];
__device__ __half g_o16  [ROWS * DIM];
__device__ __half g_gt16 [ROWS * FF_DIM];
__device__ __half g_q16 [ROWS * DIM];
__device__ __half g_k16 [OUT_KV_ELEMS];
__device__ __half g_v16 [OUT_KV_ELEMS];
__device__ __half g_wqkv[3 * DIM * DIM];
__device__ __half g_wo  [DIM * DIM];
__device__ __half g_wg  [DIM * FF_DIM];
__device__ __half g_wv2 [DIM * FF_DIM];
__device__ __half g_wp  [FF_DIM * DIM];

// =====================================================================
// prep kernel (proven): rmsnorm rows + weight conversion tiles.
// =====================================================================
__global__ __launch_bounds__(256) void prep_kernel(
    const float* __restrict__ x, const float* __restrict__ anw,
    __half* __restrict__ hA,
    const float* __restrict__ wq, const float* __restrict__ wk,
    const float* __restrict__ wv, const float* __restrict__ wo,
    const float* __restrict__ wg, const float* __restrict__ wv2,
    const float* __restrict__ wp,
    __half* __restrict__ Tqkv, __half* __restrict__ Two,
    __half* __restrict__ Twg, __half* __restrict__ Twv2,
    __half* __restrict__ Twp)
{
    __shared__ float sm[32 * 133];
    const int tid = threadIdx.x;
    const int bid = blockIdx.x;

    if (bid < ROWS) {
        const float* xp = x + (size_t)bid * DIM + tid * 8;
        float4 a = *(const float4*)xp;
        float4 b = *(const float4*)(xp + 4);
        float s = a.x*a.x + a.y*a.y + a.z*a.z + a.w*a.w
                + b.x*b.x + b.y*b.y + b.z*b.z + b.w*b.w;
        sm[tid] = s;
        __syncthreads();
        #pragma unroll
        for (int off = 128; off > 0; off >>= 1) {
            if (tid < off) sm[tid] += sm[tid + off];
            __syncthreads();
        }
        float scale = rsqrtf(sm[0] * (1.0f / DIM) + 1e-6f);
        const float* wpt = anw + tid * 8;
        float4 wa = *(const float4*)wpt;
        float4 wb = *(const float4*)(wpt + 4);
        float y[8];
        y[0] = a.x*scale*wa.x; y[1] = a.y*scale*wa.y; y[2] = a.z*scale*wa.z; y[3] = a.w*scale*wa.w;
        y[4] = b.x*scale*wb.x; y[5] = b.y*scale*wb.y; y[6] = b.z*scale*wb.z; y[7] = b.w*scale*wb.w;
        __align__(16) __half hv[8];
        #pragma unroll
        for (int j = 0; j < 8; j++) hv[j] = __float2half(y[j]);
        *(uint4*)(hA + (size_t)bid * DIM + tid * 8) = *(const uint4*)hv;
        return;
    }

    const int cid = bid - ROWS;
    const float* W; __half* T; int N, K, kb, nb;
    if (cid < 3072) {
        const int mat = cid / 1024, b = cid % 1024;
        W = (mat == 0) ? wq : ((mat == 1) ? wk : wv);
        T = Tqkv + (size_t)mat * DIM * DIM;
        N = DIM; K = DIM; kb = b % 64; nb = b / 64;
    } else if (cid < 4096) {
        const int b = cid - 3072;
        W = wo; T = Two; N = DIM; K = DIM; kb = b % 64; nb = b / 64;
    } else if (cid < 8192) {
        const int b = cid - 4096;
        W = wg; T = Twg; N = FF_DIM; K = DIM; kb = b % 64; nb = b / 64;
    } else if (cid < 12288) {
        const int b = cid - 8192;
        W = wv2; T = Twv2; N = FF_DIM; K = DIM; kb = b % 64; nb = b / 64;
    } else {
        const int b = cid - 12288;
        W = wp; T = Twp; N = DIM; K = FF_DIM; kb = b % 256; nb = b / 256;
    }
    const int k0 = kb * 32, n0 = nb * 128;
    {
        const int kr = tid >> 3;
        const int nq = (tid & 7) * 16;
        const float* src = W + (size_t)(k0 + kr) * N + n0 + nq;
        #pragma unroll
        for (int u = 0; u < 4; u++) {
            float4 v = *(const float4*)(src + u * 4);
            sm[kr * 133 + nq + u * 4 + 0] = v.x;
            sm[kr * 133 + nq + u * 4 + 1] = v.y;
            sm[kr * 133 + nq + u * 4 + 2] = v.z;
            sm[kr * 133 + nq + u * 4 + 3] = v.w;
        }
    }
    __syncthreads();
    const int n = tid >> 1;
    const int q = tid & 1;
    __align__(16) __half hv[16];
    #pragma unroll
    for (int u = 0; u < 16; u++)
        hv[u] = __float2half(sm[(q * 16 + u) * 133 + n]);
    const size_t off = (size_t)(n0 + n) * K + k0 + q * 16;
    *(uint4*)(T + off)     = *(const uint4*)(hv);
    *(uint4*)(T + off + 8) = *(const uint4*)(hv + 8);
}

// =====================================================================
// rmsnorm -> single fp16 row-major (ffn block)
// =====================================================================
__global__ __launch_bounds__(256) void rmsnorm_h(
    const float* __restrict__ x, const float* __restrict__ w,
    __half* __restrict__ O16)
{
    __shared__ float red[256];
    const int tid = threadIdx.x;
    const int m = blockIdx.x;
    const float* xp = x + (size_t)m * DIM + tid * 8;
    float4 a = *(const float4*)xp;
    float4 b = *(const float4*)(xp + 4);
    float s = a.x*a.x + a.y*a.y + a.z*a.z + a.w*a.w
            + b.x*b.x + b.y*b.y + b.z*b.z + b.w*b.w;
    red[tid] = s;
    __syncthreads();
    #pragma unroll
    for (int off = 128; off > 0; off >>= 1) {
        if (tid < off) red[tid] += red[tid + off];
        __syncthreads();
    }
    float scale = rsqrtf(red[0] * (1.0f / DIM) + 1e-6f);
    const float* wp = w + tid * 8;
    float4 wa = *(const float4*)wp;
    float4 wb = *(const float4*)(wp + 4);
    float y[8];
    y[0] = a.x*scale*wa.x; y[1] = a.y*scale*wa.y; y[2] = a.z*scale*wa.z; y[3] = a.w*scale*wa.w;
    y[4] = b.x*scale*wb.x; y[5] = b.y*scale*wb.y; y[6] = b.z*scale*wb.z; y[7] = b.w*scale*wb.w;
    __align__(16) __half hv[8];
    #pragma unroll
    for (int j = 0; j < 8; j++) hv[j] = __float2half(y[j]);
    *(uint4*)(O16 + (size_t)m * DIM + tid * 8) = *(const uint4*)hv;
}

// =====================================================================
// Shared swizzle for 64B rows (K-chunk 32 fp16)
// =====================================================================
__device__ __forceinline__ uint32_t swz(int r, int g) {
    return (uint32_t)(r * 64 + ((g ^ ((r >> 1) & 3)) << 4));
}

// =====================================================================
// 2-CTA/SM GEMM core: CTA 128(M)x128(N), warp 64x32 (2m x 4n), 8 warps,
// K-chunk 32, 6-stage x 16KB cp.async ring. ldsm batched before mmas.
// =====================================================================
#define G2_STAGES 6
#define G2_STAGE_BYTES 16384
#define G2_SMEM (G2_STAGES * G2_STAGE_BYTES)   // 98304
#define G2_OFF_A 0
#define G2_OFF_B 8192

#define G2_ISSUE_LAMBDA(A16, B16, m0, n0, K)                                    \
    auto issue_stage = [&](int kc, int slot) {                                  \
        const uint32_t st = sb + slot * G2_STAGE_BYTES;                         \
        const int kelem = kc * 32 + lg * 8;                                     \
        _Pragma("unroll")                                                       \
        for (int i = 0; i < 2; i++) {                                           \
            const int r = lr + i * 64;                                          \
            const uint32_t sw = swz(r, lg);                                     \
            cp_async16(st + G2_OFF_A + sw, A16 + (size_t)(m0 + r) * K + kelem); \
            cp_async16(st + G2_OFF_B + sw, B16 + (size_t)(n0 + r) * K + kelem); \
        }                                                                       \
    };

template<typename IssueF>
__device__ __forceinline__ void g2_mainloop(
    float (&acc)[4][4][4], uint32_t sb, int nk, int wm, int wn, int lane,
    IssueF issue_stage)
{
    #pragma unroll
    for (int p = 0; p < 5; p++) { issue_stage(p, p); CP_COMMIT(); }

    int slot = 0, slotN = 5;
    for (int kc = 0; kc < nk; kc++) {
        CP_WAIT4();
        __syncthreads();
        if (kc + 5 < nk) issue_stage(kc + 5, slotN);
        CP_COMMIT();

        const uint32_t st = sb + slot * G2_STAGE_BYTES;
        #pragma unroll
        for (int h = 0; h < 2; h++) {
            uint32_t a[4][4], b0[4], b1[4];
            #pragma unroll
            for (int mi = 0; mi < 4; mi++) {
                const int r = wm * 64 + mi * 16 + (lane & 15);
                ldsm4(a[mi], st + G2_OFF_A + swz(r, h * 2 + (lane >> 4)));
            }
            {
                const int r0 = wn * 32 + (lane & 15);
                ldsm4(b0, st + G2_OFF_B + swz(r0, h * 2 + (lane >> 4)));
                ldsm4(b1, st + G2_OFF_B + swz(r0 + 16, h * 2 + (lane >> 4)));
            }
            #pragma unroll
            for (int mi = 0; mi < 4; mi++) {
                mma_f16(acc[mi][0], a[mi], b0[0], b0[2]);
                mma_f16(acc[mi][1], a[mi], b0[1], b0[3]);
                mma_f16(acc[mi][2], a[mi], b1[0], b1[2]);
                mma_f16(acc[mi][3], a[mi], b1[1], b1[3]);
            }
        }
        slot  = (slot  == G2_STAGES - 1) ? 0 : slot + 1;
        slotN = (slotN == G2_STAGES - 1) ? 0 : slotN + 1;
    }
}

// =====================================================================
// Generic GEMM v2 (MODE 1): C = A@B + bias + extra (fp32 out)
// =====================================================================
template<int MODE>
__global__ void __launch_bounds__(256, 2) gemm_mma2(
    const __half* __restrict__ A16, const __half* __restrict__ B16,
    const float* __restrict__ bias, const float* __restrict__ extra,
    float* __restrict__ C, int M, int N, int K)
{
    extern __shared__ char smraw[];
    const uint32_t sb = smem_u32(smraw);
    const int tid = threadIdx.x;
    const int wid = tid >> 5;
    const int lane = tid & 31;
    const int wm = wid & 1;
    const int wn = wid >> 1;
    const int m0 = blockIdx.y * 128;
    const int n0 = blockIdx.x * 128;
    const int nk = K >> 5;
    const int lr = tid >> 2;
    const int lg = tid & 3;

    float acc[4][4][4];
    #pragma unroll
    for (int a = 0; a < 4; a++)
        #pragma unroll
        for (int b = 0; b < 4; b++)
            #pragma unroll
            for (int c = 0; c < 4; c++) acc[a][b][c] = 0.f;

    G2_ISSUE_LAMBDA(A16, B16, m0, n0, K)
    g2_mainloop(acc, sb, nk, wm, wn, lane, issue_stage);

    const int mb = m0 + wm * 64;
    const int nb = n0 + wn * 32;
    #pragma unroll
    for (int mi = 0; mi < 4; mi++) {
        #pragma unroll
        for (int j = 0; j < 4; j++) {
            const int row = mb + mi * 16 + (lane >> 2);
            const int col = nb + j * 8 + (lane & 3) * 2;
            const float b0 = bias[col], b1 = bias[col + 1];
            #pragma unroll
            for (int half = 0; half < 2; half++) {
                const int rr = row + half * 8;
                float v0 = acc[mi][j][half * 2 + 0] + b0;
                float v1 = acc[mi][j][half * 2 + 1] + b1;
                if (MODE == 1) {
                    const float* ep = extra + (size_t)rr * N + col;
                    v0 += ep[0]; v1 += ep[1];
                }
                *(float2*)(C + (size_t)rr * N + col) = make_float2(v0, v1);
            }
        }
    }
}

// =====================================================================
// Fused QKV GEMM v2 + cache copy. B = concat[wq|wk|wv] (N=6144).
// grid (50, 32): bx < 48 -> 128x128 GEMM tile; bx >= 48 -> copy CTA.
// =====================================================================
__global__ void __launch_bounds__(256, 2) gemm_qkv2(
    const __half* __restrict__ A16, const __half* __restrict__ B16,
    const float* __restrict__ bq, const float* __restrict__ bk, const float* __restrict__ bv,
    const float* __restrict__ cosb, const float* __restrict__ sinb,
    const float* __restrict__ k_cache, const float* __restrict__ v_cache,
    float* __restrict__ out_k, float* __restrict__ out_v,
    __half* __restrict__ Q16, __half* __restrict__ K16, __half* __restrict__ V16)
{
    extern __shared__ char smraw[];
    const int tid = threadIdx.x;

    if (blockIdx.x >= 48) {
        const int cidx = (blockIdx.x - 48) * 32 + blockIdx.y;
        for (int idx = cidx * 256 + tid; idx < (1 << 21); idx += 64 * 256) {
            const int z = idx >> 20;
            const int i = idx & ((1 << 20) - 1);
            const float* in = z ? v_cache : k_cache;
            float* out = z ? out_v : out_k;
            __half* H16 = z ? V16 : K16;
            const int bh  = i >> 15;
            const int rem = i & 32767;
            float4 v = ((const float4*)in)[i];
            size_t off4 = (size_t)bh * (T_LEN * HD / 4) + rem;
            ((float4*)out)[off4] = v;
            __align__(8) __half hv[4];
            hv[0] = __float2half(v.x); hv[1] = __float2half(v.y);
            hv[2] = __float2half(v.z); hv[3] = __float2half(v.w);
            *(uint2*)(H16 + off4 * 4) = *(const uint2*)hv;
        }
        return;
    }

    const uint32_t sb = smem_u32(smraw);
    const int wid = tid >> 5;
    const int lane = tid & 31;
    const int wm = wid & 1;
    const int wn = wid >> 1;
    const int m0 = blockIdx.y * 128;
    const int n0 = blockIdx.x * 128;
    const int K = DIM;
    const int nk = K >> 5;
    const int lr = tid >> 2;
    const int lg = tid & 3;
    const int sec = n0 >> 11;
    const float* bias = (sec == 0) ? bq : ((sec == 1) ? bk : bv);

    float acc[4][4][4];
    #pragma unroll
    for (int a = 0; a < 4; a++)
        #pragma unroll
        for (int b = 0; b < 4; b++)
            #pragma unroll
            for (int c = 0; c < 4; c++) acc[a][b][c] = 0.f;

    G2_ISSUE_LAMBDA(A16, B16, m0, n0, K)
    g2_mainloop(acc, sb, nk, wm, wn, lane, issue_stage);

    const int mb = m0 + wm * 64;
    const int nb = n0 + wn * 32;
    #pragma unroll
    for (int mi = 0; mi < 4; mi++) {
        #pragma unroll
        for (int j = 0; j < 4; j++) {
            const int row = mb + mi * 16 + (lane >> 2);
            const int col = nb + j * 8 + (lane & 3) * 2;
            const float b0 = bias[col & 2047], b1 = bias[(col & 2047) + 1];
            const int nc = col & 2047;
            const int h = nc >> 7;
            const int d = nc & 127;
            #pragma unroll
            for (int half = 0; half < 2; half++) {
                const int rr = row + half * 8;
                float v0 = acc[mi][j][half * 2 + 0] + b0;
                float v1 = acc[mi][j][half * 2 + 1] + b1;
                const int bi = rr >> 11;
                const int s = rr & 2047;
                if (sec < 2) {
                    const int i2 = d >> 1;
                    const float c = cosb[(PREV_LEN + s) * 64 + i2];
                    const float sn = sinb[(PREV_LEN + s) * 64 + i2];
                    const float r0 = v0 * c - v1 * sn;
                    const float r1 = v0 * sn + v1 * c;
                    if (sec == 0) {
                        *(__half2*)(Q16 + ((size_t)(bi * HEADS + h) * S_LEN + s) * HD + d) =
                            __floats2half2_rn(r0 * QK_SCALE, r1 * QK_SCALE);
                    } else {
                        const size_t off = ((size_t)(bi * HEADS + h) * T_LEN + PREV_LEN + s) * HD + d;
                        *(float2*)(out_k + off) = make_float2(r0, r1);
                        *(__half2*)(K16 + off) = __floats2half2_rn(r0, r1);
                    }
                } else {
                    const size_t off = ((size_t)(bi * HEADS + h) * T_LEN + PREV_LEN + s) * HD + d;
                    *(float2*)(out_v + off) = make_float2(v0, v1);
                    *(__half2*)(V16 + off) = __floats2half2_rn(v0, v1);
                }
            }
        }
    }
}

// =====================================================================
// Fused FFN gate+val GEMM v2: CTA 128(M)x64(N) of BOTH matrices,
// warp tile 64x16 (2m x 4n), K-chunk 32, 6-stage x 16KB -> 2 CTAs/SM.
// stage: A 8K | Bg 4K | Bv 4K.
// =====================================================================
#define FF2_STAGE_BYTES 16384
#define FF2_SMEM (G2_STAGES * FF2_STAGE_BYTES)   // 98304
#define FF2_A  0
#define FF2_BG 8192
#define FF2_BV 12288

__global__ void __launch_bounds__(256, 2) gemm_ffn2(
    const __half* __restrict__ A16,
    const __half* __restrict__ Bg, const __half* __restrict__ Bv,
    const float* __restrict__ bias_g, const float* __restrict__ bias_v,
    __half* __restrict__ C16)
{
    extern __shared__ char smraw[];
    const uint32_t sb = smem_u32(smraw);
    const int tid = threadIdx.x;
    const int wid = tid >> 5;
    const int lane = tid & 31;
    const int wm = wid & 1;
    const int wn = wid >> 1;       // 0..3, warp n-offset = wn*16
    const int m0 = blockIdx.y * 128;
    const int n0 = blockIdx.x * 64;
    const int K = DIM;
    const int nk = K >> 5;
    const int lr = tid >> 2;       // 0..63
    const int lg = tid & 3;

    float ag[4][2][4], av[4][2][4];
    #pragma unroll
    for (int a = 0; a < 4; a++)
        #pragma unroll
        for (int b = 0; b < 2; b++)
            #pragma unroll
            for (int c = 0; c < 4; c++) { ag[a][b][c] = 0.f; av[a][b][c] = 0.f; }

    auto issue_stage = [&](int kc, int slot) {
        const uint32_t st = sb + slot * FF2_STAGE_BYTES;
        const int kelem = kc * 32 + lg * 8;
        const uint32_t sw = swz(lr, lg);
        #pragma unroll
        for (int i = 0; i < 2; i++) {
            const int r = lr + i * 64;
            cp_async16(st + FF2_A + swz(r, lg), A16 + (size_t)(m0 + r) * K + kelem);
        }
        cp_async16(st + FF2_BG + sw, Bg + (size_t)(n0 + lr) * K + kelem);
        cp_async16(st + FF2_BV + sw, Bv + (size_t)(n0 + lr) * K + kelem);
    };

    #pragma unroll
    for (int p = 0; p < 5; p++) { issue_stage(p, p); CP_COMMIT(); }

    int slot = 0, slotN = 5;
    for (int kc = 0; kc < nk; kc++) {
        CP_WAIT4();
        __syncthreads();
        if (kc + 5 < nk) issue_stage(kc + 5, slotN);
        CP_COMMIT();

        const uint32_t st = sb + slot * FF2_STAGE_BYTES;
        #pragma unroll
        for (int h = 0; h < 2; h++) {
            uint32_t a[4][4], bg[4], bv[4];
            #pragma unroll
            for (int mi = 0; mi < 4; mi++) {
                const int r = wm * 64 + mi * 16 + (lane & 15);
                ldsm4(a[mi], st + FF2_A + swz(r, h * 2 + (lane >> 4)));
            }
            {
                const int r = wn * 16 + (lane & 15);
                const uint32_t sw2 = swz(r, h * 2 + (lane >> 4));
                ldsm4(bg, st + FF2_BG + sw2);
                ldsm4(bv, st + FF2_BV + sw2);
            }
            #pragma unroll
            for (int mi = 0; mi < 4; mi++) {
                mma_f16(ag[mi][0], a[mi], bg[0], bg[2]);
                mma_f16(ag[mi][1], a[mi], bg[1], bg[3]);
                mma_f16(av[mi][0], a[mi], bv[0], bv[2]);
                mma_f16(av[mi][1], a[mi], bv[1], bv[3]);
            }
        }
        slot  = (slot  == G2_STAGES - 1) ? 0 : slot + 1;
        slotN = (slotN == G2_STAGES - 1) ? 0 : slotN + 1;
    }

    const int mb = m0 + wm * 64;
    const int nb = n0 + wn * 16;
    #pragma unroll
    for (int mi = 0; mi < 4; mi++) {
        #pragma unroll
        for (int j = 0; j < 2; j++) {
            const int row = mb + mi * 16 + (lane >> 2);
            const int col = nb + j * 8 + (lane & 3) * 2;
            const float bg0 = bias_g[col], bg1 = bias_g[col + 1];
            const float bv0 = bias_v[col], bv1 = bias_v[col + 1];
            #pragma unroll
            for (int half = 0; half < 2; half++) {
                const int rr = row + half * 8;
                float gv0 = ag[mi][j][half * 2 + 0] + bg0;
                float gv1 = ag[mi][j][half * 2 + 1] + bg1;
                float vv0 = av[mi][j][half * 2 + 0] + bv0;
                float vv1 = av[mi][j][half * 2 + 1] + bv1;
                float o0 = gv0 / (1.f + __expf(-gv0)) * vv0;
                float o1 = gv1 / (1.f + __expf(-gv1)) * vv1;
                *(__half2*)(C16 + (size_t)rr * FF_DIM + col) = __floats2half2_rn(o0, o1);
            }
        }
    }
}

// =====================================================================
// HMMA flash attention (proven): fp16 1-pass QK, 3-stage KV,
// single barrier per tile.
// =====================================================================
#define FBM 128
#define FBN 64
#define F_OFF_Q  0
#define F_OFF_ST 32768
#define F_STAGE  32768
#define F_SMEM   (F_OFF_ST + 3 * F_STAGE)   // 131072

__device__ __forceinline__ uint32_t swz256(int r, int g) {
    return (uint32_t)((r << 8) + (((g ^ (r & 7)) & 15) << 4));
}

__global__ void __launch_bounds__(256) flash_mma(
    const __half* __restrict__ Q16, const __half* __restrict__ K16,
    const __half* __restrict__ V16, __half* __restrict__ O16)
{
    extern __shared__ char smraw[];
    const uint32_t sb = smem_u32(smraw);
    const int tid = threadIdx.x;
    const int wid = tid >> 5;
    const int lane = tid & 31;
    const int mtile = gridDim.x - 1 - blockIdx.x;
    const int bh = blockIdx.y;
    const int m0 = mtile * FBM;
    const int jend = (PREV_LEN + m0 + FBM) / FBN;
    const int mask_start = (PREV_LEN + m0) / FBN;

    {
        const size_t qo = ((size_t)bh * S_LEN + m0) * HD;
        for (int i = tid; i < 2048; i += 256) {
            int r = i >> 4, g = i & 15;
            cp_async16(sb + F_OFF_Q + swz256(r, g), Q16 + qo + (size_t)r * HD + g * 8);
        }
        CP_COMMIT();
    }

    auto issue_kv = [&](int jt, int slot) {
        const uint32_t st = sb + F_OFF_ST + slot * F_STAGE;
        const size_t ko = ((size_t)bh * T_LEN + jt * FBN) * HD;
        for (int i = tid; i < 1024; i += 256) {
            int r = i >> 4, g = i & 15;
            uint32_t sw = swz256(r, g);
            size_t go = ko + (size_t)r * HD + g * 8;
            cp_async16(st + sw, K16 + go);
            cp_async16(st + 16384 + sw, V16 + go);
        }
    };
    issue_kv(0, 0); CP_COMMIT();
    issue_kv(1, 1); CP_COMMIT();

    float of[16][4];
    #pragma unroll
    for (int i = 0; i < 16; i++)
        #pragma unroll
        for (int j = 0; j < 4; j++) of[i][j] = 0.f;
    float mrow0 = -1e30f, mrow1 = -1e30f, lrow0 = 0.f, lrow1 = 0.f;

    const int arow = wid * 16 + (lane & 15);
    const int agr  = lane >> 4;

    int slot = 0;
    int slot2 = 2;
    for (int jt = 0; jt < jend; jt++) {
        CP_WAIT1();
        __syncthreads();
        if (jt + 2 < jend) issue_kv(jt + 2, slot2);
        CP_COMMIT();

        const uint32_t st = sb + F_OFF_ST + slot * F_STAGE;
        const int t0 = jt * FBN;

        float sf[8][4];
        #pragma unroll
        for (int i = 0; i < 8; i++)
            #pragma unroll
            for (int j = 0; j < 4; j++) sf[i][j] = 0.f;

        #pragma unroll
        for (int kt = 0; kt < 8; kt++) {
            uint32_t a[4];
            ldsm4(a, sb + F_OFF_Q + swz256(arow, kt * 2 + agr));
            #pragma unroll
            for (int nb = 0; nb < 4; nb++) {
                uint32_t b[4];
                ldsm4(b, st + swz256(nb * 16 + (lane & 15), kt * 2 + agr));
                mma_f16(sf[nb * 2 + 0], a, b[0], b[2]);
                mma_f16(sf[nb * 2 + 1], a, b[1], b[3]);
            }
        }

        if (jt >= mask_start) {
            const int rb = m0 + wid * 16 + (lane >> 2);
            const int cb = t0 + (lane & 3) * 2;
            #pragma unroll
            for (int nt = 0; nt < 8; nt++) {
                const int c0 = cb + nt * 8;
                if (c0     > PREV_LEN + rb)     sf[nt][0] = -1e30f;
                if (c0 + 1 > PREV_LEN + rb)     sf[nt][1] = -1e30f;
                if (c0     > PREV_LEN + rb + 8) sf[nt][2] = -1e30f;
                if (c0 + 1 > PREV_LEN + rb + 8) sf[nt][3] = -1e30f;
            }
        }

        float mx0 = -1e30f, mx1 = -1e30f;
        #pragma unroll
        for (int nt = 0; nt < 8; nt++) {
            mx0 = fmaxf(mx0, fmaxf(sf[nt][0], sf[nt][1]));
            mx1 = fmaxf(mx1, fmaxf(sf[nt][2], sf[nt][3]));
        }
        mx0 = fmaxf(mx0, __shfl_xor_sync(0xFFFFFFFF, mx0, 1));
        mx0 = fmaxf(mx0, __shfl_xor_sync(0xFFFFFFFF, mx0, 2));
        mx1 = fmaxf(mx1, __shfl_xor_sync(0xFFFFFFFF, mx1, 1));
        mx1 = fmaxf(mx1, __shfl_xor_sync(0xFFFFFFFF, mx1, 2));
        const float nm0 = fmaxf(mrow0, mx0);
        const float nm1 = fmaxf(mrow1, mx1);
        const float al0 = __expf(mrow0 - nm0);
        const float al1 = __expf(mrow1 - nm1);
        mrow0 = nm0; mrow1 = nm1;

        float rs0 = 0.f, rs1 = 0.f;
        #pragma unroll
        for (int nt = 0; nt < 8; nt++) {
            sf[nt][0] = __expf(sf[nt][0] - nm0);
            sf[nt][1] = __expf(sf[nt][1] - nm0);
            sf[nt][2] = __expf(sf[nt][2] - nm1);
            sf[nt][3] = __expf(sf[nt][3] - nm1);
            rs0 += sf[nt][0] + sf[nt][1];
            rs1 += sf[nt][2] + sf[nt][3];
        }
        rs0 += __shfl_xor_sync(0xFFFFFFFF, rs0, 1);
        rs0 += __shfl_xor_sync(0xFFFFFFFF, rs0, 2);
        rs1 += __shfl_xor_sync(0xFFFFFFFF, rs1, 1);
        rs1 += __shfl_xor_sync(0xFFFFFFFF, rs1, 2);
        lrow0 = lrow0 * al0 + rs0;
        lrow1 = lrow1 * al1 + rs1;

        #pragma unroll
        for (int nt = 0; nt < 16; nt++) {
            of[nt][0] *= al0; of[nt][1] *= al0;
            of[nt][2] *= al1; of[nt][3] *= al1;
        }

        #pragma unroll
        for (int kt = 0; kt < 4; kt++) {
            uint32_t a[4];
            a[0] = pack_f16(sf[2 * kt][0],     sf[2 * kt][1]);
            a[1] = pack_f16(sf[2 * kt][2],     sf[2 * kt][3]);
            a[2] = pack_f16(sf[2 * kt + 1][0], sf[2 * kt + 1][1]);
            a[3] = pack_f16(sf[2 * kt + 1][2], sf[2 * kt + 1][3]);
            const int vrow = kt * 16 + ((lane >> 3) & 1) * 8 + (lane & 7);
            #pragma unroll
            for (int nb = 0; nb < 8; nb++) {
                uint32_t b[4];
                ldsm4t(b, st + 16384 + swz256(vrow, nb * 2 + ((lane >> 4) & 1)));
                mma_f16(of[nb * 2 + 0], a, b[0], b[1]);
                mma_f16(of[nb * 2 + 1], a, b[2], b[3]);
            }
        }
        slot  = (slot  == 2) ? 0 : slot + 1;
        slot2 = (slot2 == 2) ? 0 : slot2 + 1;
    }

    const float inv0 = 1.f / lrow0;
    const float inv1 = 1.f / lrow1;
    const int b = bh >> 4, h = bh & 15;
    const int r0 = m0 + wid * 16 + (lane >> 2);
    #pragma unroll
    for (int nt = 0; nt < 16; nt++) {
        const int gc = h * HD + nt * 8 + (lane & 3) * 2;
        *(__half2*)(O16 + (size_t)(b * S_LEN + r0) * DIM + gc) =
            __floats2half2_rn(of[nt][0] * inv0, of[nt][1] * inv0);
        *(__half2*)(O16 + (size_t)(b * S_LEN + r0 + 8) * DIM + gc) =
            __floats2half2_rn(of[nt][2] * inv1, of[nt][3] * inv1);
    }
}

// ---------------- launch ----------------
extern "C" void kernel_launch(void* const* d_in, const int* in_sizes, int n_in,
                              void* d_out, int out_size)
{
    const float* x          = (const float*)d_in[0];
    const float* k_cache    = (const float*)d_in[1];
    const float* v_cache    = (const float*)d_in[2];
    const float* attn_norm_w= (const float*)d_in[3];
    const float* ffn_norm_w = (const float*)d_in[4];
    const float* wq = (const float*)d_in[5];
    const float* bq = (const float*)d_in[6];
    const float* wk = (const float*)d_in[7];
    const float* bk = (const float*)d_in[8];
    const float* wv = (const float*)d_in[9];
    const float* bv = (const float*)d_in[10];
    const float* wo = (const float*)d_in[11];
    const float* bo = (const float*)d_in[12];
    const float* w_gate = (const float*)d_in[13];
    const float* b_gate = (const float*)d_in[14];
    const float* w_val  = (const float*)d_in[15];
    const float* b_val  = (const float*)d_in[16];
    const float* w_proj = (const float*)d_in[17];
    const float* b_proj = (const float*)d_in[18];
    const float* fcos   = (const float*)d_in[19];
    const float* fsin   = (const float*)d_in[20];

    float* out_x = (float*)d_out;
    float* out_k = out_x + OUT_X_ELEMS;
    float* out_v = out_k + OUT_KV_ELEMS;

    float *p_x1;
    __half *p_hA16, *p_h216, *p_o16, *p_gt16;
    __half *p_q16, *p_k16, *p_v16;
    __half *p_wqkv, *p_wo, *p_wg, *p_wv2, *p_wp;

    cudaGetSymbolAddress((void**)&p_x1, g_x1);
    cudaGetSymbolAddress((void**)&p_hA16, g_hA16);
    cudaGetSymbolAddress((void**)&p_h216, g_h216);
    cudaGetSymbolAddress((void**)&p_o16,  g_o16);
    cudaGetSymbolAddress((void**)&p_gt16, g_gt16);
    cudaGetSymbolAddress((void**)&p_q16,  g_q16);
    cudaGetSymbolAddress((void**)&p_k16,  g_k16);
    cudaGetSymbolAddress((void**)&p_v16,  g_v16);
    cudaGetSymbolAddress((void**)&p_wqkv, g_wqkv);
    cudaGetSymbolAddress((void**)&p_wo,   g_wo);
    cudaGetSymbolAddress((void**)&p_wg,   g_wg);
    cudaGetSymbolAddress((void**)&p_wv2,  g_wv2);
    cudaGetSymbolAddress((void**)&p_wp,   g_wp);

    cudaFuncSetAttribute(gemm_mma2<1>, cudaFuncAttributeMaxDynamicSharedMemorySize, G2_SMEM);
    cudaFuncSetAttribute(gemm_qkv2,  cudaFuncAttributeMaxDynamicSharedMemorySize, G2_SMEM);
    cudaFuncSetAttribute(gemm_ffn2,  cudaFuncAttributeMaxDynamicSharedMemorySize, FF2_SMEM);
    cudaFuncSetAttribute(flash_mma,  cudaFuncAttributeMaxDynamicSharedMemorySize, F_SMEM);

    // ---- prep: rmsnorm(attn) + all weight conversions in one grid ----
    prep_kernel<<<ROWS + 16384, 256>>>(
        x, attn_norm_w, p_hA16,
        wq, wk, wv, wo, w_gate, w_val, w_proj,
        p_wqkv, p_wo, p_wg, p_wv2, p_wp);

    // ---- attention block (qkv GEMM + fused cache copy) ----
    gemm_qkv2<<<dim3(50, 32), 256, G2_SMEM>>>(
        p_hA16, p_wqkv, bq, bk, bv, fcos, fsin,
        k_cache, v_cache, out_k, out_v, p_q16, p_k16, p_v16);

    flash_mma<<<dim3(S_LEN / FBM, BATCH * HEADS), 256, F_SMEM>>>(
        p_q16, p_k16, p_v16, p_o16);

    gemm_mma2<1><<<dim3(16, 32), 256, G2_SMEM>>>(
        p_o16, p_wo, bo, x, p_x1, ROWS, DIM, DIM);

    // ---- ffn block ----
    rmsnorm_h<<<ROWS, 256>>>(p_x1, ffn_norm_w, p_h216);
    gemm_ffn2<<<dim3(128, 32), 256, FF2_SMEM>>>(
        p_h216, p_wg, p_wv2, b_gate, b_val, p_gt16);
    gemm_mma2<1><<<dim3(16, 32), 256, G2_SMEM>>>(
        p_gt16, p_wp, b_proj, p_x1, out_x, ROWS, DIM, FF_DIM);
}